// round 3
// baseline (speedup 1.0000x reference)
#include <cuda_runtime.h>
#include <cuda_bf16.h>
#include <stdint.h>

#define BB   32
#define TT   20
#define HH   100
#define GG   300      // 3H
#define DD   200      // 2H
#define KK   200      // GEMM K
#define VV   32000

// ---------------- scratch (static device globals; no allocation) ----------------
__device__ float g_gx0f[BB*TT*GG];
__device__ float g_gx0b[BB*TT*GG];
__device__ float g_y0  [BB*TT*DD];
__device__ float g_gx1 [BB*TT*2*GG];   // combined fwd|bwd, row stride 600
__device__ float g_y1  [BB*TT*DD];

// ================= helpers =================
__device__ __forceinline__ uint32_t smem_u32(const void* p) {
    uint32_t a;
    asm("{ .reg .u64 t; cvta.to.shared.u64 t, %1; cvt.u32.u64 %0, t; }" : "=r"(a) : "l"(p));
    return a;
}
#define MBARRIER_INIT(addr, cnt) \
    asm volatile("mbarrier.init.shared.b64 [%0], %1;" :: "r"((uint32_t)(addr)), "r"((uint32_t)(cnt)) : "memory")
#define MBARRIER_ARRIVE(addr) \
    asm volatile("mbarrier.arrive.release.cta.shared::cta.b64 _, [%0];" :: "r"((uint32_t)(addr)) : "memory")
#define MBARRIER_WAIT_PARITY(addr, par) do { \
    uint32_t _m = (uint32_t)(addr), _p = (uint32_t)(par), _d; \
    asm volatile("{\n\t.reg .pred p;\n\t" \
        "mbarrier.try_wait.parity.acquire.cta.shared::cta.b64 p, [%1], %2;\n\t" \
        "selp.b32 %0, 1, 0, p;\n\t}" : "=r"(_d) : "r"(_m), "r"(_p) : "memory"); \
    if (!_d) { \
        asm volatile("{\n\t.reg .pred P1;\n\tWL_%=:\n\t" \
            "mbarrier.try_wait.parity.acquire.cta.shared::cta.b64 P1, [%0], %1, 0x989680;\n\t" \
            "@P1 bra.uni WD_%=;\n\tbra.uni WL_%=;\n\tWD_%=:\n\t}" \
            :: "r"(_m), "r"(_p) : "memory"); \
    } } while(0)

__device__ __forceinline__ void ldsm4(uint32_t* r, uint32_t addr) {
    asm volatile("ldmatrix.sync.aligned.m8n8.x4.shared.b16 {%0,%1,%2,%3}, [%4];"
        : "=r"(r[0]), "=r"(r[1]), "=r"(r[2]), "=r"(r[3]) : "r"(addr));
}
__device__ __forceinline__ void mma16816(float* c, const uint32_t* a,
                                         uint32_t b0, uint32_t b1) {
    asm volatile("mma.sync.aligned.m16n8k16.row.col.f32.bf16.bf16.f32 "
        "{%0,%1,%2,%3}, {%4,%5,%6,%7}, {%8,%9}, {%0,%1,%2,%3};"
        : "+f"(c[0]), "+f"(c[1]), "+f"(c[2]), "+f"(c[3])
        : "r"(a[0]), "r"(a[1]), "r"(a[2]), "r"(a[3]), "r"(b0), "r"(b1));
}
__device__ __forceinline__ void split2(float a, float b, uint32_t& hi, uint32_t& lo) {
    __nv_bfloat16 ha = __float2bfloat16(a), hb = __float2bfloat16(b);
    __nv_bfloat16 la = __float2bfloat16(a - __bfloat162float(ha));
    __nv_bfloat16 lb = __float2bfloat16(b - __bfloat162float(hb));
    __nv_bfloat162 h2 = __halves2bfloat162(ha, hb), l2 = __halves2bfloat162(la, lb);
    hi = *reinterpret_cast<uint32_t*>(&h2);
    lo = *reinterpret_cast<uint32_t*>(&l2);
}

// ---------------- embedding gather --------------------------------
__global__ void gather_kernel(const int* __restrict__ x,
                              const float* __restrict__ Wf,
                              const float* __restrict__ Wb) {
    int tok = blockIdx.x;
    int v   = x[tok];
    int tid = threadIdx.x;
    if (tid < GG) g_gx0f[tok*GG + tid]      = Wf[tid*VV + v];
    else          g_gx0b[tok*GG + (tid-GG)] = Wb[(tid-GG)*VV + v];
}

// ---------------- GRU: one CTA per (dir, batch) ----------------------
__global__ __launch_bounds__(320) void gru_kernel(
    const float* __restrict__ gxf, const float* __restrict__ gxb, int ldg_,
    const float* __restrict__ Whhf, const float* __restrict__ Whhb,
    const float* __restrict__ hidden, int hid_base,
    float* __restrict__ y, float* __restrict__ hout)
{
    int dir = blockIdx.x >> 5;
    int b   = blockIdx.x & 31;
    const float* gx  = dir ? gxb  : gxf;
    const float* Whh = dir ? Whhb : Whhf;
    int g = threadIdx.x;

    __shared__ __align__(16) float h_s[HH];
    __shared__ float gh_s[GG];
    __shared__ float gx_s[GG];

    float w[HH];
    if (g < GG) {
        #pragma unroll
        for (int k = 0; k < HH; k++) w[k] = Whh[g*HH + k];
    }
    if (g < HH) h_s[g] = hidden[(hid_base + dir)*BB*HH + b*HH + g];
    __syncthreads();

    for (int t = 0; t < TT; t++) {
        int tt = dir ? (TT-1-t) : t;
        if (g < GG) {
            float gxv = gx[(size_t)(b*TT + tt)*ldg_ + g];
            float acc = 0.f;
            const float4* h4 = reinterpret_cast<const float4*>(h_s);
            #pragma unroll
            for (int kk = 0; kk < HH/4; kk++) {
                float4 hv = h4[kk];
                acc += w[4*kk+0]*hv.x + w[4*kk+1]*hv.y
                     + w[4*kk+2]*hv.z + w[4*kk+3]*hv.w;
            }
            gh_s[g] = acc;
            gx_s[g] = gxv;
        }
        __syncthreads();
        if (g < HH) {
            float r = 1.f/(1.f + __expf(-(gx_s[g]    + gh_s[g])));
            float z = 1.f/(1.f + __expf(-(gx_s[HH+g] + gh_s[HH+g])));
            float n = tanhf(gx_s[2*HH+g] + r*gh_s[2*HH+g]);
            float hn = (1.f - z)*n + z*h_s[g];
            h_s[g] = hn;
            y[(b*TT + tt)*DD + dir*HH + g] = hn;
        }
        __syncthreads();
    }
    if (g < HH) hout[(hid_base + dir)*BB*HH + b*HH + g] = h_s[g];
}

// ================= pipelined split-bf16 GEMM (mma.sync) ======================
// C[640, Ntot] = A[640,200] * B[Ntot,200]^T, 3-pass hi/lo bf16 (err ~2^-18).
// Persistent CTA owns one 128-row m-block (A split once into smem) and loops
// over 64-col n-tiles. 8 compute warps + 4 producer warps; B tiles stream
// through a 2-slot smem ring (mbarrier full/empty). KP=216 padding gives
// conflict-free ldmatrix.
#define KP   216
#define BMM  128
#define BNN  64
#define KCN  13            // 13*16 = 208 >= 200 (padding zeroed)

// smem byte offsets
#define SO_FULL   0        // full[2] mbarriers
#define SO_EMPTY  16       // empty[2]
#define SO_AHI    1024
#define SO_ALO    (SO_AHI + BMM*KP*2)        // 56320
#define SO_B0     (SO_ALO + BMM*KP*2)        // 111616
#define B_SLOT_BY (BNN*KP*2*2)               // 55296 (hi+lo)
#define B_HALF_BY (BNN*KP*2)                 // 27648
#define GEMM_SMEM (SO_B0 + 2*B_SLOT_BY)      // 222208

__global__ __launch_bounds__(384, 1) void pg_gemm(
    const float* __restrict__ A,
    const float* __restrict__ B1, const float* __restrict__ B2, int N1,
    int Ntot, float* __restrict__ C, int ldc, int gpm)
{
    extern __shared__ __align__(16) unsigned char dsm[];
    const uint32_t sb = smem_u32(dsm);
    const int tid = threadIdx.x;
    const int bid = blockIdx.x;
    const int m   = bid % 5;
    const int c   = bid / 5;
    const int m0  = m * BMM;
    const int ntn = (Ntot + BNN - 1) / BNN;

    if (tid == 0) {
        MBARRIER_INIT(sb + SO_FULL + 0, 128);
        MBARRIER_INIT(sb + SO_FULL + 8, 128);
        MBARRIER_INIT(sb + SO_EMPTY + 0, 256);
        MBARRIER_INIT(sb + SO_EMPTY + 8, 256);
    }

    // zero K-pad (cols 200..215) of A (2 halves) and both B slots (2 halves each)
    // 6 half-regions x (rows*8 u32 words)
    for (int i = tid; i < (BMM*2 + BNN*4) * 8; i += 384) {
        int reg = i / (BMM*8);           // 0,1 -> A halves; >=2 -> B halves
        uint32_t base;
        int r, w;
        if (reg < 2) {
            int j = i - reg*(BMM*8);
            r = j >> 3; w = j & 7;
            base = sb + (reg ? SO_ALO : SO_AHI);
        } else {
            int j = i - 2*(BMM*8);
            int h = j / (BNN*8);         // 0..3
            int jj = j - h*(BNN*8);
            r = jj >> 3; w = jj & 7;
            base = sb + SO_B0 + (h >> 1)*B_SLOT_BY + (h & 1)*B_HALF_BY;
        }
        uint32_t addr = base + ((uint32_t)r*KP + 200)*2 + (uint32_t)w*4;
        asm volatile("st.shared.b32 [%0], %1;" :: "r"(addr), "r"(0u) : "memory");
    }

    // cooperative A load + split (128 rows x 200 cols = 3200 float4 x2... 6400/384)
    for (int i = tid; i < BMM*(KK/4); i += 384) {
        int row = i / (KK/4), c4 = (i % (KK/4)) * 4;
        float4 v = *reinterpret_cast<const float4*>(A + (size_t)(m0+row)*KK + c4);
        uint32_t h0, h1, l0, l1;
        split2(v.x, v.y, h0, l0);
        split2(v.z, v.w, h1, l1);
        uint32_t off = ((uint32_t)row*KP + (uint32_t)c4)*2;
        asm volatile("st.shared.v2.b32 [%0], {%1,%2};" :: "r"(sb + SO_AHI + off), "r"(h0), "r"(h1) : "memory");
        asm volatile("st.shared.v2.b32 [%0], {%1,%2};" :: "r"(sb + SO_ALO + off), "r"(l0), "r"(l1) : "memory");
    }
    __syncthreads();

    if (tid >= 256) {
        // ================= producer warps (8..11, 128 threads) =================
        const int ptid = tid - 256;
        int ep[2] = {0, 0};
        int j = 0;
        for (;; j++) {
            int n = c + j * gpm;
            if (n >= ntn) break;
            const int n0 = n * BNN;
            const int slot = j & 1;
            if (j >= 2) {
                MBARRIER_WAIT_PARITY(sb + SO_EMPTY + slot*8, ep[slot]);
                ep[slot] ^= 1;
            }
            const uint32_t bh = sb + SO_B0 + slot*B_SLOT_BY;
            const uint32_t bl = bh + B_HALF_BY;
            #pragma unroll
            for (int it = 0; it < (BNN*(KK/4))/128; it++) {   // 25 iters
                int u   = ptid + it*128;
                int row = u / (KK/4);
                int c4  = (u % (KK/4)) * 4;
                int gr  = n0 + row;
                float4 v = make_float4(0.f, 0.f, 0.f, 0.f);
                if (gr < Ntot) {
                    const float* src = (gr < N1) ? (B1 + (size_t)gr*KK)
                                                 : (B2 + (size_t)(gr - N1)*KK);
                    v = *reinterpret_cast<const float4*>(src + c4);
                }
                uint32_t h0, h1, l0, l1;
                split2(v.x, v.y, h0, l0);
                split2(v.z, v.w, h1, l1);
                uint32_t off = ((uint32_t)row*KP + (uint32_t)c4)*2;
                asm volatile("st.shared.v2.b32 [%0], {%1,%2};" :: "r"(bh + off), "r"(h0), "r"(h1) : "memory");
                asm volatile("st.shared.v2.b32 [%0], {%1,%2};" :: "r"(bl + off), "r"(l0), "r"(l1) : "memory");
            }
            MBARRIER_ARRIVE(sb + SO_FULL + slot*8);
        }
    } else {
        // ================= compute warps (0..7) =================
        const int wid = tid >> 5, lane = tid & 31;
        const int wm = wid & 3;            // 4 m-blocks of 32
        const int wn = wid >> 2;           // 2 n-blocks of 32
        const int lr = lane & 7, lq = lane >> 3;

        const uint32_t aRow = (uint32_t)(wm*32 + (lq & 1)*8 + lr);
        const uint32_t aCol = (uint32_t)((lq >> 1)*8);
        const uint32_t bRow = (uint32_t)(wn*32 + (lq >> 1)*8 + lr);
        const uint32_t bCol = (uint32_t)((lq & 1)*8);

        const uint32_t aHiB = sb + SO_AHI + (aRow*KP + aCol)*2;
        const uint32_t aLoB = sb + SO_ALO + (aRow*KP + aCol)*2;
        uint32_t bHiB[2], bLoB[2];
        #pragma unroll
        for (int s = 0; s < 2; s++) {
            bHiB[s] = sb + SO_B0 + s*B_SLOT_BY + (bRow*KP + bCol)*2;
            bLoB[s] = bHiB[s] + B_HALF_BY;
        }

        int fp[2] = {0, 0};
        int j = 0;
        for (;; j++) {
            int n = c + j * gpm;
            if (n >= ntn) break;
            const int n0 = n * BNN;
            const int slot = j & 1;
            MBARRIER_WAIT_PARITY(sb + SO_FULL + slot*8, fp[slot]);
            fp[slot] ^= 1;

            float acc[2][4][4];
            #pragma unroll
            for (int mt = 0; mt < 2; mt++)
                #pragma unroll
                for (int nt = 0; nt < 4; nt++)
                    #pragma unroll
                    for (int q = 0; q < 4; q++) acc[mt][nt][q] = 0.f;

            #pragma unroll
            for (int kc = 0; kc < KCN; kc++) {
                const uint32_t kOff = (uint32_t)(kc*16) * 2;
                uint32_t ah[2][4], al[2][4], bh[2][4], bl[2][4];
                #pragma unroll
                for (int mt = 0; mt < 2; mt++) {
                    uint32_t o = (uint32_t)(mt*16*KP)*2 + kOff;
                    ldsm4(ah[mt], aHiB + o);
                    ldsm4(al[mt], aLoB + o);
                }
                #pragma unroll
                for (int nt2 = 0; nt2 < 2; nt2++) {
                    uint32_t o = (uint32_t)(nt2*16*KP)*2 + kOff;
                    ldsm4(bh[nt2], bHiB[slot] + o);
                    ldsm4(bl[nt2], bLoB[slot] + o);
                }
                #pragma unroll
                for (int mt = 0; mt < 2; mt++)
                    #pragma unroll
                    for (int nt = 0; nt < 4; nt++) {
                        const uint32_t* bhp = &bh[nt >> 1][(nt & 1)*2];
                        const uint32_t* blp = &bl[nt >> 1][(nt & 1)*2];
                        mma16816(acc[mt][nt], ah[mt], bhp[0], bhp[1]);
                        mma16816(acc[mt][nt], al[mt], bhp[0], bhp[1]);
                        mma16816(acc[mt][nt], ah[mt], blp[0], blp[1]);
                    }
            }
            MBARRIER_ARRIVE(sb + SO_EMPTY + slot*8);   // slot free before epilogue

            // epilogue from registers
            const int r0 = m0 + wm*32 + (lane >> 2);
            const int c0 = n0 + wn*32 + (lane & 3)*2;
            #pragma unroll
            for (int mt = 0; mt < 2; mt++)
                #pragma unroll
                for (int nt = 0; nt < 4; nt++) {
                    int row = r0 + mt*16;
                    int col = c0 + nt*8;
                    if (col < Ntot) {
                        *reinterpret_cast<float2*>(C + (size_t)row*ldc + col) =
                            make_float2(acc[mt][nt][0], acc[mt][nt][1]);
                        *reinterpret_cast<float2*>(C + (size_t)(row+8)*ldc + col) =
                            make_float2(acc[mt][nt][2], acc[mt][nt][3]);
                    }
                }
        }
    }
}

// ---------------- launch ----------------
extern "C" void kernel_launch(void* const* d_in, const int* in_sizes, int n_in,
                              void* d_out, int out_size) {
    const int*   x      = (const int*)  d_in[0];
    const float* hidden = (const float*)d_in[1];
    const float* Wih0f  = (const float*)d_in[2];
    const float* Whh0f  = (const float*)d_in[3];
    const float* Wih0b  = (const float*)d_in[4];
    const float* Whh0b  = (const float*)d_in[5];
    const float* Wih1f  = (const float*)d_in[6];
    const float* Whh1f  = (const float*)d_in[7];
    const float* Wih1b  = (const float*)d_in[8];
    const float* Whh1b  = (const float*)d_in[9];
    const float* Wlin   = (const float*)d_in[10];

    float* out  = (float*)d_out;
    float* hout = out + (out_size - 4*BB*HH);

    void *p_gx0f, *p_gx0b, *p_y0, *p_gx1, *p_y1;
    cudaGetSymbolAddress(&p_gx0f, g_gx0f);
    cudaGetSymbolAddress(&p_gx0b, g_gx0b);
    cudaGetSymbolAddress(&p_y0,   g_y0);
    cudaGetSymbolAddress(&p_gx1,  g_gx1);
    cudaGetSymbolAddress(&p_y1,   g_y1);

    cudaFuncSetAttribute(pg_gemm, cudaFuncAttributeMaxDynamicSharedMemorySize, GEMM_SMEM);

    // 1. embedding gather
    gather_kernel<<<BB*TT, 2*GG>>>(x, Wih0f, Wih0b);

    // 2. GRU layer 0
    gru_kernel<<<64, 320>>>((const float*)p_gx0f, (const float*)p_gx0b, GG,
                            Whh0f, Whh0b, hidden, 0, (float*)p_y0, hout);

    // 3. fused layer-1 projections: g_gx1[:,0:300]=y0@Wih1f^T, [:,300:600]=y0@Wih1b^T
    //    Ntot=600 -> 10 n-tiles; grid = 5 m-groups x 10 CTAs
    pg_gemm<<<50, 384, GEMM_SMEM>>>((const float*)p_y0, Wih1f, Wih1b, GG,
                                    2*GG, (float*)p_gx1, 2*GG, 10);

    // 4. GRU layer 1 (reads combined gx1 with stride 600)
    gru_kernel<<<64, 320>>>((const float*)p_gx1, (const float*)p_gx1 + GG, 2*GG,
                            Whh1f, Whh1b, hidden, 2, (float*)p_y1, hout);

    // 5. final projection: out = y1 @ Wlin^T  [640 x 32000], 500 n-tiles,
    //    grid = 5 x 29 = 145 persistent CTAs (~18 tiles each)
    pg_gemm<<<145, 384, GEMM_SMEM>>>((const float*)p_y1, Wlin, Wlin, VV,
                                     VV, out, VV, 29);
}

// round 5
// speedup vs baseline: 1.9698x; 1.9698x over previous
#include <cuda_runtime.h>
#include <cuda_bf16.h>
#include <stdint.h>

#define BB   32
#define TT   20
#define HH   100
#define GG   300      // 3H
#define DD   200      // 2H
#define KK   200      // GEMM K
#define VV   32000

// ---------------- scratch (static device globals; no allocation) ----------------
__device__ float g_gx0f[BB*TT*GG];
__device__ float g_gx0b[BB*TT*GG];
__device__ float g_y0  [BB*TT*DD];
__device__ float g_gx1 [BB*TT*2*GG];   // combined fwd|bwd, row stride 600
__device__ float g_y1  [BB*TT*DD];

// ================= helpers =================
__device__ __forceinline__ uint32_t smem_u32(const void* p) {
    uint32_t a;
    asm("{ .reg .u64 t; cvta.to.shared.u64 t, %1; cvt.u32.u64 %0, t; }" : "=r"(a) : "l"(p));
    return a;
}
__device__ __forceinline__ void ldsm4(uint32_t* r, uint32_t addr) {
    asm volatile("ldmatrix.sync.aligned.m8n8.x4.shared.b16 {%0,%1,%2,%3}, [%4];"
        : "=r"(r[0]), "=r"(r[1]), "=r"(r[2]), "=r"(r[3]) : "r"(addr));
}
__device__ __forceinline__ void mma16816(float* c, const uint32_t* a,
                                         uint32_t b0, uint32_t b1) {
    asm volatile("mma.sync.aligned.m16n8k16.row.col.f32.bf16.bf16.f32 "
        "{%0,%1,%2,%3}, {%4,%5,%6,%7}, {%8,%9}, {%0,%1,%2,%3};"
        : "+f"(c[0]), "+f"(c[1]), "+f"(c[2]), "+f"(c[3])
        : "r"(a[0]), "r"(a[1]), "r"(a[2]), "r"(a[3]), "r"(b0), "r"(b1));
}
__device__ __forceinline__ void split2(float a, float b, uint32_t& hi, uint32_t& lo) {
    __nv_bfloat16 ha = __float2bfloat16(a), hb = __float2bfloat16(b);
    __nv_bfloat16 la = __float2bfloat16(a - __bfloat162float(ha));
    __nv_bfloat16 lb = __float2bfloat16(b - __bfloat162float(hb));
    __nv_bfloat162 h2 = __halves2bfloat162(ha, hb), l2 = __halves2bfloat162(la, lb);
    hi = *reinterpret_cast<uint32_t*>(&h2);
    lo = *reinterpret_cast<uint32_t*>(&l2);
}
#define STS32(addr, v) \
    asm volatile("st.shared.b32 [%0], %1;" :: "r"(addr), "r"(v) : "memory")

// ---------------- embedding gather --------------------------------
__global__ void gather_kernel(const int* __restrict__ x,
                              const float* __restrict__ Wf,
                              const float* __restrict__ Wb) {
    int tok = blockIdx.x;
    int v   = x[tok];
    int tid = threadIdx.x;
    if (tid < GG) g_gx0f[tok*GG + tid]      = Wf[tid*VV + v];
    else          g_gx0b[tok*GG + (tid-GG)] = Wb[(tid-GG)*VV + v];
}

// ---------------- GRU: one CTA per (dir, batch), 2 threads per gate ----------
__global__ __launch_bounds__(640) void gru_kernel(
    const float* __restrict__ gxf, const float* __restrict__ gxb, int ldg_,
    const float* __restrict__ Whhf, const float* __restrict__ Whhb,
    const float* __restrict__ hidden, int hid_base,
    float* __restrict__ y, float* __restrict__ hout)
{
    int dir = blockIdx.x >> 5;
    int b   = blockIdx.x & 31;
    const float* gx  = dir ? gxb  : gxf;
    const float* Whh = dir ? Whhb : Whhf;
    int tid  = threadIdx.x;
    int g    = tid >> 1;
    int half = tid & 1;
    bool act = (g < GG);

    __shared__ __align__(16) float h_s[104];   // 100 + 4 zero pad
    __shared__ float gh_s[GG];
    __shared__ float gx_s[GG];

    const int base = half * 52;
    const int wcnt = half ? 48 : 52;
    float w[52];
    #pragma unroll
    for (int k = 0; k < 52; k++)
        w[k] = (act && k < wcnt) ? Whh[g*HH + base + k] : 0.f;

    if (tid < HH)  h_s[tid] = hidden[(hid_base + dir)*BB*HH + b*HH + tid];
    if (tid >= HH && tid < 104) h_s[tid] = 0.f;
    __syncthreads();

    for (int t = 0; t < TT; t++) {
        int tt = dir ? (TT-1-t) : t;
        const float* grow = gx + (size_t)(b*TT + tt) * ldg_;
        if (tid < GG) gx_s[tid] = grow[tid];

        float a0 = 0.f, a1 = 0.f, a2 = 0.f, a3 = 0.f;
        const float4* h4 = reinterpret_cast<const float4*>(h_s + base);
        #pragma unroll
        for (int kk = 0; kk < 13; kk++) {
            float4 hv = h4[kk];
            a0 += w[4*kk+0]*hv.x; a1 += w[4*kk+1]*hv.y;
            a2 += w[4*kk+2]*hv.z; a3 += w[4*kk+3]*hv.w;
        }
        float dot = (a0 + a1) + (a2 + a3);
        dot += __shfl_xor_sync(0xffffffffu, dot, 1);
        if (act && half == 0) gh_s[g] = dot;
        __syncthreads();

        if (tid < HH) {
            float r  = 1.f/(1.f + __expf(-(gx_s[tid]     + gh_s[tid])));
            float z  = 1.f/(1.f + __expf(-(gx_s[HH+tid]  + gh_s[HH+tid])));
            float nn = tanhf(gx_s[2*HH+tid] + r*gh_s[2*HH+tid]);
            float hn = (1.f - z)*nn + z*h_s[tid];
            h_s[tid] = hn;
            y[(b*TT + tt)*DD + dir*HH + tid] = hn;
        }
        __syncthreads();
    }
    if (tid < HH) hout[(hid_base + dir)*BB*HH + b*HH + tid] = h_s[tid];
}

// ================= reg-prefetch split-bf16 GEMM (mma.sync) ==================
// C[640, Ntot] = A[640,200] * B[Ntot,200]^T, 3-pass hi/lo bf16.
// A tile = 128 rows (12800 float2, 25 iters/512thr). B tile = 64 rows
// (6400 float2, 13 iters with guard).
#define KP   216
#define KC   13
#define SO_AHI   0
#define SO_ALO   55296
#define SO_B0    110592
#define B_SLOT   55296
#define B_HALF   27648
#define GEMM_SMEM 221184
#define BIT  13            // B tile iterations (ceil(6400/512))

__global__ __launch_bounds__(512, 1) void pg_gemm(
    const float* __restrict__ A,
    const float* __restrict__ B1, const float* __restrict__ B2, int N1,
    int Ntot, float* __restrict__ C, int ldc)
{
    extern __shared__ __align__(16) unsigned char dsm[];
    const uint32_t sb = smem_u32(dsm);
    const int tid = threadIdx.x;
    const int m0  = blockIdx.x * 128;
    const int c   = blockIdx.y;
    const int S   = gridDim.y;
    const int ntn = (Ntot + 63) / 64;
    if (c >= ntn) return;

    // ---- zero K pads (cols 200..207): A hi/lo + B 2 slots x 2 halves ----
    {
        int row = tid >> 2, wd = tid & 3;   // 512 = 128 rows * 4 words
        uint32_t off = ((uint32_t)row*KP + 200)*2 + (uint32_t)wd*4;
        STS32(sb + SO_AHI + off, 0u);
        STS32(sb + SO_ALO + off, 0u);
        // B pads: 4 half-regions x 64 rows x 4 words = 1024 items
        #pragma unroll
        for (int q = 0; q < 2; q++) {
            int i = tid + q*512;
            int reg = i >> 8;                 // 0..3
            int j   = i & 255;
            int br  = j >> 2, bw = j & 3;     // br < 64
            uint32_t bbase = sb + SO_B0 + (uint32_t)(reg >> 1)*B_SLOT
                           + (uint32_t)(reg & 1)*B_HALF;
            STS32(bbase + ((uint32_t)br*KP + 200)*2 + (uint32_t)bw*4, 0u);
        }
    }

    // ---- prologue prefetch of first B tile into registers (64 rows) ----
    float2 pf[BIT];
    {
        const int n0 = c * 64;
        #pragma unroll
        for (int i = 0; i < BIT; i++) {
            int u = tid + i*512;
            float2 v = make_float2(0.f, 0.f);
            if (u < 6400) {
                int row = u / 100, c2 = u % 100;
                int gr = n0 + row;
                if (gr < Ntot) {
                    const float* src = (gr < N1) ? (B1 + (size_t)gr*KK)
                                                 : (B2 + (size_t)(gr - N1)*KK);
                    v = *reinterpret_cast<const float2*>(src + c2*2);
                }
            }
            pf[i] = v;
        }
    }

    // ---- load + split A m-block (once; exactly 25 iters) ----
    #pragma unroll
    for (int i = 0; i < 25; i++) {
        int u = tid + i*512;
        int row = u / 100, c2 = u % 100;
        float2 v = *reinterpret_cast<const float2*>(A + (size_t)(m0+row)*KK + c2*2);
        uint32_t h, l;
        split2(v.x, v.y, h, l);
        uint32_t off = ((uint32_t)row*KP + (uint32_t)c2*2)*2;
        STS32(sb + SO_AHI + off, h);
        STS32(sb + SO_ALO + off, l);
    }

    // ---- per-warp ldmatrix addressing ----
    const int wid = tid >> 5, lane = tid & 31;
    const int wm = wid & 3;            // 4 m-blocks of 32
    const int wn = wid >> 2;           // 4 n-blocks of 16
    const int lr = lane & 7, lq = lane >> 3;

    const uint32_t aRow = (uint32_t)(wm*32 + (lq & 1)*8 + lr);
    const uint32_t aCol = (uint32_t)((lq >> 1)*8);
    const uint32_t bRow = (uint32_t)(wn*16 + (lq >> 1)*8 + lr);
    const uint32_t bCol = (uint32_t)((lq & 1)*8);

    const uint32_t aHiB = sb + SO_AHI + (aRow*KP + aCol)*2;
    const uint32_t aLoB = sb + SO_ALO + (aRow*KP + aCol)*2;
    uint32_t bHiB[2], bLoB[2];
    #pragma unroll
    for (int s = 0; s < 2; s++) {
        bHiB[s] = sb + SO_B0 + (uint32_t)s*B_SLOT + (bRow*KP + bCol)*2;
        bLoB[s] = bHiB[s] + B_HALF;
    }

    int phase = 0;
    for (int t = c; t < ntn; t += S, phase++) {
        const int slot = phase & 1;
        const int n0   = t * 64;

        // ---- store split of prefetched B tile into smem slot ----
        {
            const uint32_t bh = sb + SO_B0 + (uint32_t)slot*B_SLOT;
            #pragma unroll
            for (int i = 0; i < BIT; i++) {
                int u = tid + i*512;
                if (u < 6400) {
                    int row = u / 100, c2 = u % 100;
                    uint32_t h, l;
                    split2(pf[i].x, pf[i].y, h, l);
                    uint32_t off = ((uint32_t)row*KP + (uint32_t)c2*2)*2;
                    STS32(bh + off, h);
                    STS32(bh + B_HALF + off, l);
                }
            }
        }
        __syncthreads();

        // ---- prefetch next tile (overlaps compute below) ----
        const int tn = t + S;
        if (tn < ntn) {
            const int nn0 = tn * 64;
            #pragma unroll
            for (int i = 0; i < BIT; i++) {
                int u = tid + i*512;
                float2 v = make_float2(0.f, 0.f);
                if (u < 6400) {
                    int row = u / 100, c2 = u % 100;
                    int gr = nn0 + row;
                    if (gr < Ntot) {
                        const float* src = (gr < N1) ? (B1 + (size_t)gr*KK)
                                                     : (B2 + (size_t)(gr - N1)*KK);
                        v = *reinterpret_cast<const float2*>(src + c2*2);
                    }
                }
                pf[i] = v;
            }
        }

        // ---- compute ----
        float acc[2][2][4];
        #pragma unroll
        for (int mt = 0; mt < 2; mt++)
            #pragma unroll
            for (int ns = 0; ns < 2; ns++)
                #pragma unroll
                for (int q = 0; q < 4; q++) acc[mt][ns][q] = 0.f;

        #pragma unroll
        for (int kc = 0; kc < KC; kc++) {
            const uint32_t kOff = (uint32_t)kc * 32;   // 16 elems * 2B
            uint32_t ah[2][4], al[2][4], bh[4], bl[4];
            #pragma unroll
            for (int mt = 0; mt < 2; mt++) {
                uint32_t o = (uint32_t)(mt*16*KP)*2 + kOff;
                ldsm4(ah[mt], aHiB + o);
                ldsm4(al[mt], aLoB + o);
            }
            ldsm4(bh, bHiB[slot] + kOff);
            ldsm4(bl, bLoB[slot] + kOff);
            #pragma unroll
            for (int mt = 0; mt < 2; mt++)
                #pragma unroll
                for (int ns = 0; ns < 2; ns++) {
                    mma16816(acc[mt][ns], ah[mt], bh[ns*2], bh[ns*2+1]);
                    mma16816(acc[mt][ns], al[mt], bh[ns*2], bh[ns*2+1]);
                    mma16816(acc[mt][ns], ah[mt], bl[ns*2], bl[ns*2+1]);
                }
        }

        // ---- epilogue from registers ----
        const int r0 = m0 + wm*32 + (lane >> 2);
        const int c0 = n0 + wn*16 + (lane & 3)*2;
        #pragma unroll
        for (int mt = 0; mt < 2; mt++)
            #pragma unroll
            for (int ns = 0; ns < 2; ns++) {
                int row = r0 + mt*16;
                int col = c0 + ns*8;
                if (col < Ntot) {
                    *reinterpret_cast<float2*>(C + (size_t)row*ldc + col) =
                        make_float2(acc[mt][ns][0], acc[mt][ns][1]);
                    *reinterpret_cast<float2*>(C + (size_t)(row+8)*ldc + col) =
                        make_float2(acc[mt][ns][2], acc[mt][ns][3]);
                }
            }
    }
}

// ---------------- launch ----------------
extern "C" void kernel_launch(void* const* d_in, const int* in_sizes, int n_in,
                              void* d_out, int out_size) {
    const int*   x      = (const int*)  d_in[0];
    const float* hidden = (const float*)d_in[1];
    const float* Wih0f  = (const float*)d_in[2];
    const float* Whh0f  = (const float*)d_in[3];
    const float* Wih0b  = (const float*)d_in[4];
    const float* Whh0b  = (const float*)d_in[5];
    const float* Wih1f  = (const float*)d_in[6];
    const float* Whh1f  = (const float*)d_in[7];
    const float* Wih1b  = (const float*)d_in[8];
    const float* Whh1b  = (const float*)d_in[9];
    const float* Wlin   = (const float*)d_in[10];

    float* out  = (float*)d_out;
    float* hout = out + (out_size - 4*BB*HH);

    void *p_gx0f, *p_gx0b, *p_y0, *p_gx1, *p_y1;
    cudaGetSymbolAddress(&p_gx0f, g_gx0f);
    cudaGetSymbolAddress(&p_gx0b, g_gx0b);
    cudaGetSymbolAddress(&p_y0,   g_y0);
    cudaGetSymbolAddress(&p_gx1,  g_gx1);
    cudaGetSymbolAddress(&p_y1,   g_y1);

    cudaFuncSetAttribute(pg_gemm, cudaFuncAttributeMaxDynamicSharedMemorySize, GEMM_SMEM);

    // 1. embedding gather
    gather_kernel<<<BB*TT, 2*GG>>>(x, Wih0f, Wih0b);

    // 2. GRU layer 0
    gru_kernel<<<64, 640>>>((const float*)p_gx0f, (const float*)p_gx0b, GG,
                            Whh0f, Whh0b, hidden, 0, (float*)p_y0, hout);

    // 3. fused layer-1 projections (Ntot=600 -> 10 tiles; grid 5x10)
    pg_gemm<<<dim3(5, 10), 512, GEMM_SMEM>>>((const float*)p_y0, Wih1f, Wih1b,
                                             GG, 2*GG, (float*)p_gx1, 2*GG);

    // 4. GRU layer 1 (combined gx1, stride 600)
    gru_kernel<<<64, 640>>>((const float*)p_gx1, (const float*)p_gx1 + GG, 2*GG,
                            Whh1f, Whh1b, hidden, 2, (float*)p_y1, hout);

    // 5. final projection: 500 tiles, grid 5x29 persistent (17-18 tiles/CTA)
    pg_gemm<<<dim3(5, 29), 512, GEMM_SMEM>>>((const float*)p_y1, Wlin, Wlin,
                                             VV, VV, out, VV);
}

// round 6
// speedup vs baseline: 2.0246x; 1.0278x over previous
#include <cuda_runtime.h>
#include <cuda_bf16.h>
#include <stdint.h>

#define BB   32
#define TT   20
#define HH   100
#define GG   300      // 3H
#define DD   200      // 2H
#define KK   200      // GEMM K
#define VV   32000

// ---------------- scratch (static device globals; no allocation) ----------------
__device__ float g_gx0f[BB*TT*GG];
__device__ float g_gx0b[BB*TT*GG];
__device__ float g_y0  [BB*TT*DD];
__device__ float g_gx1 [BB*TT*2*GG];   // combined fwd|bwd, row stride 600
__device__ float g_y1  [BB*TT*DD];

// ================= helpers =================
__device__ __forceinline__ uint32_t smem_u32(const void* p) {
    uint32_t a;
    asm("{ .reg .u64 t; cvta.to.shared.u64 t, %1; cvt.u32.u64 %0, t; }" : "=r"(a) : "l"(p));
    return a;
}
__device__ __forceinline__ void ldsm4(uint32_t* r, uint32_t addr) {
    asm volatile("ldmatrix.sync.aligned.m8n8.x4.shared.b16 {%0,%1,%2,%3}, [%4];"
        : "=r"(r[0]), "=r"(r[1]), "=r"(r[2]), "=r"(r[3]) : "r"(addr));
}
__device__ __forceinline__ void mma16816(float* c, const uint32_t* a,
                                         uint32_t b0, uint32_t b1) {
    asm volatile("mma.sync.aligned.m16n8k16.row.col.f32.bf16.bf16.f32 "
        "{%0,%1,%2,%3}, {%4,%5,%6,%7}, {%8,%9}, {%0,%1,%2,%3};"
        : "+f"(c[0]), "+f"(c[1]), "+f"(c[2]), "+f"(c[3])
        : "r"(a[0]), "r"(a[1]), "r"(a[2]), "r"(a[3]), "r"(b0), "r"(b1));
}
__device__ __forceinline__ void split2(float a, float b, uint32_t& hi, uint32_t& lo) {
    __nv_bfloat16 ha = __float2bfloat16(a), hb = __float2bfloat16(b);
    __nv_bfloat16 la = __float2bfloat16(a - __bfloat162float(ha));
    __nv_bfloat16 lb = __float2bfloat16(b - __bfloat162float(hb));
    __nv_bfloat162 h2 = __halves2bfloat162(ha, hb), l2 = __halves2bfloat162(la, lb);
    hi = *reinterpret_cast<uint32_t*>(&h2);
    lo = *reinterpret_cast<uint32_t*>(&l2);
}
#define STS32(addr, v) \
    asm volatile("st.shared.b32 [%0], %1;" :: "r"(addr), "r"(v) : "memory")

// ---------------- embedding gather --------------------------------
__global__ void gather_kernel(const int* __restrict__ x,
                              const float* __restrict__ Wf,
                              const float* __restrict__ Wb) {
    int tok = blockIdx.x;
    int v   = x[tok];
    int tid = threadIdx.x;
    if (tid < GG) g_gx0f[tok*GG + tid]      = Wf[tid*VV + v];
    else          g_gx0b[tok*GG + (tid-GG)] = Wb[(tid-GG)*VV + v];
}

// ---------------- GRU: one CTA per (dir, batch), 2 threads per gate ----------
// All 20 gx rows preloaded into smem at entry (latency paid once, high MLP);
// the 20-step recurrence then runs purely from smem + registers.
__global__ __launch_bounds__(640) void gru_kernel(
    const float* __restrict__ gxf, const float* __restrict__ gxb, int ldg_,
    const float* __restrict__ Whhf, const float* __restrict__ Whhb,
    const float* __restrict__ hidden, int hid_base,
    float* __restrict__ y, float* __restrict__ hout)
{
    int dir = blockIdx.x >> 5;
    int b   = blockIdx.x & 31;
    const float* gx  = dir ? gxb  : gxf;
    const float* Whh = dir ? Whhb : Whhf;
    int tid  = threadIdx.x;
    int g    = tid >> 1;
    int half = tid & 1;
    bool act = (g < GG);

    __shared__ __align__(16) float h_s[104];       // 100 + 4 zero pad
    __shared__ float gh_s[GG];
    __shared__ __align__(8) float gx_all[TT*GG];   // 24 KB: all timesteps

    // ---- preload all gx rows (float2, coalesced, full MLP) ----
    for (int i = tid; i < TT*(GG/2); i += 640) {
        int row = i / (GG/2);
        int c2  = i - row*(GG/2);
        *reinterpret_cast<float2*>(gx_all + row*GG + c2*2) =
            *reinterpret_cast<const float2*>(gx + (size_t)(b*TT + row)*ldg_ + c2*2);
    }

    // ---- weights into registers (52/48 split per thread pair) ----
    const int base = half * 52;
    const int wcnt = half ? 48 : 52;
    float w[52];
    #pragma unroll
    for (int k = 0; k < 52; k++)
        w[k] = (act && k < wcnt) ? Whh[g*HH + base + k] : 0.f;

    if (tid < HH)  h_s[tid] = hidden[(hid_base + dir)*BB*HH + b*HH + tid];
    if (tid >= HH && tid < 104) h_s[tid] = 0.f;
    __syncthreads();

    for (int t = 0; t < TT; t++) {
        int tt = dir ? (TT-1-t) : t;
        const float* gxr = gx_all + tt*GG;

        float a0 = 0.f, a1 = 0.f, a2 = 0.f, a3 = 0.f;
        const float4* h4 = reinterpret_cast<const float4*>(h_s + base);
        #pragma unroll
        for (int kk = 0; kk < 13; kk++) {
            float4 hv = h4[kk];
            a0 += w[4*kk+0]*hv.x; a1 += w[4*kk+1]*hv.y;
            a2 += w[4*kk+2]*hv.z; a3 += w[4*kk+3]*hv.w;
        }
        float dot = (a0 + a1) + (a2 + a3);
        dot += __shfl_xor_sync(0xffffffffu, dot, 1);
        if (act && half == 0) gh_s[g] = dot;
        __syncthreads();

        if (tid < HH) {
            float r  = 1.f/(1.f + __expf(-(gxr[tid]      + gh_s[tid])));
            float z  = 1.f/(1.f + __expf(-(gxr[HH+tid]   + gh_s[HH+tid])));
            float nn = tanhf(gxr[2*HH+tid] + r*gh_s[2*HH+tid]);
            float hn = (1.f - z)*nn + z*h_s[tid];
            h_s[tid] = hn;
            y[(b*TT + tt)*DD + dir*HH + tid] = hn;
        }
        __syncthreads();
    }
    if (tid < HH) hout[(hid_base + dir)*BB*HH + b*HH + tid] = h_s[tid];
}

// ================= reg-prefetch split-bf16 GEMM (mma.sync) ==================
// C[640, Ntot] = A[640,200] * B[Ntot,200]^T, 3-pass hi/lo bf16.
#define KP   216
#define KC   13
#define SO_AHI   0
#define SO_ALO   55296
#define SO_B0    110592
#define B_SLOT   55296
#define B_HALF   27648
#define GEMM_SMEM 221184
#define BIT  13            // B tile iterations (ceil(6400/512))

__global__ __launch_bounds__(512, 1) void pg_gemm(
    const float* __restrict__ A,
    const float* __restrict__ B1, const float* __restrict__ B2, int N1,
    int Ntot, float* __restrict__ C, int ldc)
{
    extern __shared__ __align__(16) unsigned char dsm[];
    const uint32_t sb = smem_u32(dsm);
    const int tid = threadIdx.x;
    const int m0  = blockIdx.x * 128;
    const int c   = blockIdx.y;
    const int S   = gridDim.y;
    const int ntn = (Ntot + 63) / 64;
    if (c >= ntn) return;

    // ---- zero K pads (cols 200..207) ----
    {
        int row = tid >> 2, wd = tid & 3;
        uint32_t off = ((uint32_t)row*KP + 200)*2 + (uint32_t)wd*4;
        STS32(sb + SO_AHI + off, 0u);
        STS32(sb + SO_ALO + off, 0u);
        #pragma unroll
        for (int q = 0; q < 2; q++) {
            int i = tid + q*512;
            int reg = i >> 8;
            int j   = i & 255;
            int br  = j >> 2, bw = j & 3;
            uint32_t bbase = sb + SO_B0 + (uint32_t)(reg >> 1)*B_SLOT
                           + (uint32_t)(reg & 1)*B_HALF;
            STS32(bbase + ((uint32_t)br*KP + 200)*2 + (uint32_t)bw*4, 0u);
        }
    }

    // ---- prologue prefetch of first B tile into registers (64 rows) ----
    float2 pf[BIT];
    {
        const int n0 = c * 64;
        #pragma unroll
        for (int i = 0; i < BIT; i++) {
            int u = tid + i*512;
            float2 v = make_float2(0.f, 0.f);
            if (u < 6400) {
                int row = u / 100, c2 = u % 100;
                int gr = n0 + row;
                if (gr < Ntot) {
                    const float* src = (gr < N1) ? (B1 + (size_t)gr*KK)
                                                 : (B2 + (size_t)(gr - N1)*KK);
                    v = *reinterpret_cast<const float2*>(src + c2*2);
                }
            }
            pf[i] = v;
        }
    }

    // ---- load + split A m-block (once; exactly 25 iters) ----
    #pragma unroll
    for (int i = 0; i < 25; i++) {
        int u = tid + i*512;
        int row = u / 100, c2 = u % 100;
        float2 v = *reinterpret_cast<const float2*>(A + (size_t)(m0+row)*KK + c2*2);
        uint32_t h, l;
        split2(v.x, v.y, h, l);
        uint32_t off = ((uint32_t)row*KP + (uint32_t)c2*2)*2;
        STS32(sb + SO_AHI + off, h);
        STS32(sb + SO_ALO + off, l);
    }

    // ---- per-warp ldmatrix addressing ----
    const int wid = tid >> 5, lane = tid & 31;
    const int wm = wid & 3;
    const int wn = wid >> 2;
    const int lr = lane & 7, lq = lane >> 3;

    const uint32_t aRow = (uint32_t)(wm*32 + (lq & 1)*8 + lr);
    const uint32_t aCol = (uint32_t)((lq >> 1)*8);
    const uint32_t bRow = (uint32_t)(wn*16 + (lq >> 1)*8 + lr);
    const uint32_t bCol = (uint32_t)((lq & 1)*8);

    const uint32_t aHiB = sb + SO_AHI + (aRow*KP + aCol)*2;
    const uint32_t aLoB = sb + SO_ALO + (aRow*KP + aCol)*2;
    uint32_t bHiB[2], bLoB[2];
    #pragma unroll
    for (int s = 0; s < 2; s++) {
        bHiB[s] = sb + SO_B0 + (uint32_t)s*B_SLOT + (bRow*KP + bCol)*2;
        bLoB[s] = bHiB[s] + B_HALF;
    }

    int phase = 0;
    for (int t = c; t < ntn; t += S, phase++) {
        const int slot = phase & 1;
        const int n0   = t * 64;

        // ---- store split of prefetched B tile into smem slot ----
        {
            const uint32_t bh = sb + SO_B0 + (uint32_t)slot*B_SLOT;
            #pragma unroll
            for (int i = 0; i < BIT; i++) {
                int u = tid + i*512;
                if (u < 6400) {
                    int row = u / 100, c2 = u % 100;
                    uint32_t h, l;
                    split2(pf[i].x, pf[i].y, h, l);
                    uint32_t off = ((uint32_t)row*KP + (uint32_t)c2*2)*2;
                    STS32(bh + off, h);
                    STS32(bh + B_HALF + off, l);
                }
            }
        }
        __syncthreads();

        // ---- prefetch next tile (overlaps compute below) ----
        const int tn = t + S;
        if (tn < ntn) {
            const int nn0 = tn * 64;
            #pragma unroll
            for (int i = 0; i < BIT; i++) {
                int u = tid + i*512;
                float2 v = make_float2(0.f, 0.f);
                if (u < 6400) {
                    int row = u / 100, c2 = u % 100;
                    int gr = nn0 + row;
                    if (gr < Ntot) {
                        const float* src = (gr < N1) ? (B1 + (size_t)gr*KK)
                                                     : (B2 + (size_t)(gr - N1)*KK);
                        v = *reinterpret_cast<const float2*>(src + c2*2);
                    }
                }
                pf[i] = v;
            }
        }

        // ---- compute ----
        float acc[2][2][4];
        #pragma unroll
        for (int mt = 0; mt < 2; mt++)
            #pragma unroll
            for (int ns = 0; ns < 2; ns++)
                #pragma unroll
                for (int q = 0; q < 4; q++) acc[mt][ns][q] = 0.f;

        #pragma unroll
        for (int kc = 0; kc < KC; kc++) {
            const uint32_t kOff = (uint32_t)kc * 32;
            uint32_t ah[2][4], al[2][4], bh[4], bl[4];
            #pragma unroll
            for (int mt = 0; mt < 2; mt++) {
                uint32_t o = (uint32_t)(mt*16*KP)*2 + kOff;
                ldsm4(ah[mt], aHiB + o);
                ldsm4(al[mt], aLoB + o);
            }
            ldsm4(bh, bHiB[slot] + kOff);
            ldsm4(bl, bLoB[slot] + kOff);
            #pragma unroll
            for (int mt = 0; mt < 2; mt++)
                #pragma unroll
                for (int ns = 0; ns < 2; ns++) {
                    mma16816(acc[mt][ns], ah[mt], bh[ns*2], bh[ns*2+1]);
                    mma16816(acc[mt][ns], al[mt], bh[ns*2], bh[ns*2+1]);
                    mma16816(acc[mt][ns], ah[mt], bl[ns*2], bl[ns*2+1]);
                }
        }

        // ---- epilogue from registers ----
        const int r0 = m0 + wm*32 + (lane >> 2);
        const int c0 = n0 + wn*16 + (lane & 3)*2;
        #pragma unroll
        for (int mt = 0; mt < 2; mt++)
            #pragma unroll
            for (int ns = 0; ns < 2; ns++) {
                int row = r0 + mt*16;
                int col = c0 + ns*8;
                if (col < Ntot) {
                    *reinterpret_cast<float2*>(C + (size_t)row*ldc + col) =
                        make_float2(acc[mt][ns][0], acc[mt][ns][1]);
                    *reinterpret_cast<float2*>(C + (size_t)(row+8)*ldc + col) =
                        make_float2(acc[mt][ns][2], acc[mt][ns][3]);
                }
            }
    }
}

// ---------------- launch ----------------
extern "C" void kernel_launch(void* const* d_in, const int* in_sizes, int n_in,
                              void* d_out, int out_size) {
    const int*   x      = (const int*)  d_in[0];
    const float* hidden = (const float*)d_in[1];
    const float* Wih0f  = (const float*)d_in[2];
    const float* Whh0f  = (const float*)d_in[3];
    const float* Wih0b  = (const float*)d_in[4];
    const float* Whh0b  = (const float*)d_in[5];
    const float* Wih1f  = (const float*)d_in[6];
    const float* Whh1f  = (const float*)d_in[7];
    const float* Wih1b  = (const float*)d_in[8];
    const float* Whh1b  = (const float*)d_in[9];
    const float* Wlin   = (const float*)d_in[10];

    float* out  = (float*)d_out;
    float* hout = out + (out_size - 4*BB*HH);

    void *p_gx0f, *p_gx0b, *p_y0, *p_gx1, *p_y1;
    cudaGetSymbolAddress(&p_gx0f, g_gx0f);
    cudaGetSymbolAddress(&p_gx0b, g_gx0b);
    cudaGetSymbolAddress(&p_y0,   g_y0);
    cudaGetSymbolAddress(&p_gx1,  g_gx1);
    cudaGetSymbolAddress(&p_y1,   g_y1);

    cudaFuncSetAttribute(pg_gemm, cudaFuncAttributeMaxDynamicSharedMemorySize, GEMM_SMEM);

    // 1. embedding gather
    gather_kernel<<<BB*TT, 2*GG>>>(x, Wih0f, Wih0b);

    // 2. GRU layer 0
    gru_kernel<<<64, 640>>>((const float*)p_gx0f, (const float*)p_gx0b, GG,
                            Whh0f, Whh0b, hidden, 0, (float*)p_y0, hout);

    // 3. fused layer-1 projections (Ntot=600 -> 10 tiles; grid 5x10)
    pg_gemm<<<dim3(5, 10), 512, GEMM_SMEM>>>((const float*)p_y0, Wih1f, Wih1b,
                                             GG, 2*GG, (float*)p_gx1, 2*GG);

    // 4. GRU layer 1 (combined gx1, stride 600)
    gru_kernel<<<64, 640>>>((const float*)p_gx1, (const float*)p_gx1 + GG, 2*GG,
                            Whh1f, Whh1b, hidden, 2, (float*)p_y1, hout);

    // 5. final projection: 500 tiles, grid 5x29 persistent (17-18 tiles/CTA)
    pg_gemm<<<dim3(5, 29), 512, GEMM_SMEM>>>((const float*)p_y1, Wlin, Wlin,
                                             VV, VV, out, VV);
}

// round 7
// speedup vs baseline: 2.3712x; 1.1712x over previous
#include <cuda_runtime.h>
#include <cuda_bf16.h>
#include <cuda_fp16.h>
#include <stdint.h>

#define BB   32
#define TT   20
#define HH   100
#define GG   300      // 3H
#define DD   200      // 2H
#define KK   200      // GEMM K
#define VV   32000

// ---------------- scratch (static device globals; no allocation) ----------------
__device__ float g_gx0f[BB*TT*GG];
__device__ float g_gx0b[BB*TT*GG];
__device__ float g_y0  [BB*TT*DD];
__device__ float g_gx1 [BB*TT*2*GG];   // combined fwd|bwd, row stride 600
__device__ float g_y1  [BB*TT*DD];

// ================= helpers =================
__device__ __forceinline__ uint32_t smem_u32(const void* p) {
    uint32_t a;
    asm("{ .reg .u64 t; cvta.to.shared.u64 t, %1; cvt.u32.u64 %0, t; }" : "=r"(a) : "l"(p));
    return a;
}
__device__ __forceinline__ void ldsm4(uint32_t* r, uint32_t addr) {
    asm volatile("ldmatrix.sync.aligned.m8n8.x4.shared.b16 {%0,%1,%2,%3}, [%4];"
        : "=r"(r[0]), "=r"(r[1]), "=r"(r[2]), "=r"(r[3]) : "r"(addr));
}
__device__ __forceinline__ void mma_bf16(float* c, const uint32_t* a,
                                         uint32_t b0, uint32_t b1) {
    asm volatile("mma.sync.aligned.m16n8k16.row.col.f32.bf16.bf16.f32 "
        "{%0,%1,%2,%3}, {%4,%5,%6,%7}, {%8,%9}, {%0,%1,%2,%3};"
        : "+f"(c[0]), "+f"(c[1]), "+f"(c[2]), "+f"(c[3])
        : "r"(a[0]), "r"(a[1]), "r"(a[2]), "r"(a[3]), "r"(b0), "r"(b1));
}
__device__ __forceinline__ void mma_fp16(float* c, const uint32_t* a,
                                         uint32_t b0, uint32_t b1) {
    asm volatile("mma.sync.aligned.m16n8k16.row.col.f32.f16.f16.f32 "
        "{%0,%1,%2,%3}, {%4,%5,%6,%7}, {%8,%9}, {%0,%1,%2,%3};"
        : "+f"(c[0]), "+f"(c[1]), "+f"(c[2]), "+f"(c[3])
        : "r"(a[0]), "r"(a[1]), "r"(a[2]), "r"(a[3]), "r"(b0), "r"(b1));
}
__device__ __forceinline__ void split2_bf(float a, float b, uint32_t& hi, uint32_t& lo) {
    __nv_bfloat16 ha = __float2bfloat16(a), hb = __float2bfloat16(b);
    __nv_bfloat16 la = __float2bfloat16(a - __bfloat162float(ha));
    __nv_bfloat16 lb = __float2bfloat16(b - __bfloat162float(hb));
    __nv_bfloat162 h2 = __halves2bfloat162(ha, hb), l2 = __halves2bfloat162(la, lb);
    hi = *reinterpret_cast<uint32_t*>(&h2);
    lo = *reinterpret_cast<uint32_t*>(&l2);
}
__device__ __forceinline__ void split2_fp(float a, float b, uint32_t& hi, uint32_t& lo) {
    __half2 h2 = __floats2half2_rn(a, b);
    float2 hf = __half22float2(h2);
    __half2 l2 = __floats2half2_rn(a - hf.x, b - hf.y);
    hi = *reinterpret_cast<uint32_t*>(&h2);
    lo = *reinterpret_cast<uint32_t*>(&l2);
}
__device__ __forceinline__ uint32_t cvt2_fp(float a, float b) {
    __half2 h2 = __floats2half2_rn(a, b);
    return *reinterpret_cast<uint32_t*>(&h2);
}
__device__ __forceinline__ unsigned long long pack_f32x2(float lo, float hi) {
    unsigned long long r;
    asm("mov.b64 %0, {%1, %2};" : "=l"(r) : "f"(lo), "f"(hi));
    return r;
}
__device__ __forceinline__ unsigned long long fma_f32x2(
    unsigned long long a, unsigned long long b, unsigned long long c) {
    unsigned long long d;
    asm("fma.rn.f32x2 %0, %1, %2, %3;" : "=l"(d) : "l"(a), "l"(b), "l"(c));
    return d;
}
__device__ __forceinline__ void unpack_f32x2(unsigned long long v, float& lo, float& hi) {
    asm("mov.b64 {%0, %1}, %2;" : "=f"(lo), "=f"(hi) : "l"(v));
}
#define STS32(addr, v) \
    asm volatile("st.shared.b32 [%0], %1;" :: "r"(addr), "r"(v) : "memory")

// ---------------- embedding gather --------------------------------
__global__ void gather_kernel(const int* __restrict__ x,
                              const float* __restrict__ Wf,
                              const float* __restrict__ Wb) {
    int tok = blockIdx.x;
    int v   = x[tok];
    int tid = threadIdx.x;
    if (tid < GG) g_gx0f[tok*GG + tid]      = Wf[tid*VV + v];
    else          g_gx0b[tok*GG + (tid-GG)] = Wb[(tid-GG)*VV + v];
}

// ---------------- GRU: one CTA per (dir, batch), 2 threads per gate ----------
// f32x2 packed FMA dot; fast sigmoid/tanh via __expf; gx preloaded in smem.
__global__ __launch_bounds__(640) void gru_kernel(
    const float* __restrict__ gxf, const float* __restrict__ gxb, int ldg_,
    const float* __restrict__ Whhf, const float* __restrict__ Whhb,
    const float* __restrict__ hidden, int hid_base,
    float* __restrict__ y, float* __restrict__ hout)
{
    int dir = blockIdx.x >> 5;
    int b   = blockIdx.x & 31;
    const float* gx  = dir ? gxb  : gxf;
    const float* Whh = dir ? Whhb : Whhf;
    int tid  = threadIdx.x;
    int g    = tid >> 1;
    int half = tid & 1;
    bool act = (g < GG);

    __shared__ __align__(16) float h_s[104];       // 100 + 4 zero pad
    __shared__ float gh_s[GG];
    __shared__ __align__(8) float gx_all[TT*GG];   // 24 KB: all timesteps

    // ---- preload all gx rows (float2, coalesced, full MLP) ----
    for (int i = tid; i < TT*(GG/2); i += 640) {
        int row = i / (GG/2);
        int c2  = i - row*(GG/2);
        *reinterpret_cast<float2*>(gx_all + row*GG + c2*2) =
            *reinterpret_cast<const float2*>(gx + (size_t)(b*TT + row)*ldg_ + c2*2);
    }

    // ---- weights into packed f32x2 registers (52/48 split per pair) ----
    const int base = half * 52;
    const int wcnt = half ? 48 : 52;
    unsigned long long w2[26];
    #pragma unroll
    for (int k = 0; k < 26; k++) {
        float wa = (act && 2*k   < wcnt) ? Whh[g*HH + base + 2*k]   : 0.f;
        float wb = (act && 2*k+1 < wcnt) ? Whh[g*HH + base + 2*k+1] : 0.f;
        w2[k] = pack_f32x2(wa, wb);
    }

    if (tid < HH)  h_s[tid] = hidden[(hid_base + dir)*BB*HH + b*HH + tid];
    if (tid >= HH && tid < 104) h_s[tid] = 0.f;
    __syncthreads();

    for (int t = 0; t < TT; t++) {
        int tt = dir ? (TT-1-t) : t;
        const float* gxr = gx_all + tt*GG;

        unsigned long long acc0 = 0ull, acc1 = 0ull;
        const float4* h4 = reinterpret_cast<const float4*>(h_s + base);
        #pragma unroll
        for (int kk = 0; kk < 13; kk++) {
            float4 hv = h4[kk];
            acc0 = fma_f32x2(w2[2*kk],   pack_f32x2(hv.x, hv.y), acc0);
            acc1 = fma_f32x2(w2[2*kk+1], pack_f32x2(hv.z, hv.w), acc1);
        }
        float a0, a1, a2, a3;
        unpack_f32x2(acc0, a0, a1);
        unpack_f32x2(acc1, a2, a3);
        float dot = (a0 + a1) + (a2 + a3);
        dot += __shfl_xor_sync(0xffffffffu, dot, 1);
        if (act && half == 0) gh_s[g] = dot;
        __syncthreads();

        if (tid < HH) {
            float r  = __fdividef(1.f, 1.f + __expf(-(gxr[tid]    + gh_s[tid])));
            float z  = __fdividef(1.f, 1.f + __expf(-(gxr[HH+tid] + gh_s[HH+tid])));
            float u  = gxr[2*HH+tid] + r*gh_s[2*HH+tid];
            float nn = __fdividef(2.f, 1.f + __expf(-2.f*u)) - 1.f;   // tanh(u)
            float hn = (1.f - z)*nn + z*h_s[tid];
            h_s[tid] = hn;
            y[(b*TT + tt)*DD + dir*HH + tid] = hn;
        }
        __syncthreads();
    }
    if (tid < HH) hout[(hid_base + dir)*BB*HH + b*HH + tid] = h_s[tid];
}

// ================= reg-prefetch split GEMM (mma.sync), templated ============
// FP16=0: bf16 3-pass (A hi/lo, B hi/lo) — err ~2^-16. Used for projections.
// FP16=1: fp16 2-pass (A hi/lo exact, B rounded) — err ~2^-11. Final GEMM.
#define KP   216
#define KC   13
#define SO_AHI   0
#define SO_ALO   55296
#define SO_B0    110592
#define B_HALF   27648
#define SMEM3    221184            // 3-pass: 2 B slots of 2 halves
#define SMEM2    165888            // 2-pass: 2 B slots of 1 half
#define BIT  13                    // B tile iterations (ceil(6400/512))

template<int FP16>
__global__ __launch_bounds__(512, 1) void pg_gemm(
    const float* __restrict__ A,
    const float* __restrict__ B1, const float* __restrict__ B2, int N1,
    int Ntot, float* __restrict__ C, int ldc)
{
    constexpr uint32_t BSLOT = FP16 ? 27648 : 55296;
    extern __shared__ __align__(16) unsigned char dsm[];
    const uint32_t sb = smem_u32(dsm);
    const int tid = threadIdx.x;
    const int m0  = blockIdx.x * 128;
    const int c   = blockIdx.y;
    const int S   = gridDim.y;
    const int ntn = (Ntot + 63) / 64;
    if (c >= ntn) return;

    // ---- zero K pads (cols 200..207) ----
    {
        int row = tid >> 2, wd = tid & 3;
        uint32_t off = ((uint32_t)row*KP + 200)*2 + (uint32_t)wd*4;
        STS32(sb + SO_AHI + off, 0u);
        STS32(sb + SO_ALO + off, 0u);
        const int nreg = FP16 ? 2 : 4;
        for (int i = tid; i < nreg*256; i += 512) {
            int reg = i >> 8;
            int j   = i & 255;
            int br  = j >> 2, bw = j & 3;
            uint32_t bbase = FP16
                ? sb + SO_B0 + (uint32_t)reg*BSLOT
                : sb + SO_B0 + (uint32_t)(reg >> 1)*BSLOT + (uint32_t)(reg & 1)*B_HALF;
            STS32(bbase + ((uint32_t)br*KP + 200)*2 + (uint32_t)bw*4, 0u);
        }
    }

    // ---- prologue prefetch of first B tile into registers (64 rows) ----
    float2 pf[BIT];
    {
        const int n0 = c * 64;
        #pragma unroll
        for (int i = 0; i < BIT; i++) {
            int u = tid + i*512;
            float2 v = make_float2(0.f, 0.f);
            if (u < 6400) {
                int row = u / 100, c2 = u % 100;
                int gr = n0 + row;
                if (gr < Ntot) {
                    const float* src = (gr < N1) ? (B1 + (size_t)gr*KK)
                                                 : (B2 + (size_t)(gr - N1)*KK);
                    v = *reinterpret_cast<const float2*>(src + c2*2);
                }
            }
            pf[i] = v;
        }
    }

    // ---- load + split A m-block (once; exactly 25 iters) ----
    #pragma unroll
    for (int i = 0; i < 25; i++) {
        int u = tid + i*512;
        int row = u / 100, c2 = u % 100;
        float2 v = *reinterpret_cast<const float2*>(A + (size_t)(m0+row)*KK + c2*2);
        uint32_t h, l;
        if (FP16) split2_fp(v.x, v.y, h, l);
        else      split2_bf(v.x, v.y, h, l);
        uint32_t off = ((uint32_t)row*KP + (uint32_t)c2*2)*2;
        STS32(sb + SO_AHI + off, h);
        STS32(sb + SO_ALO + off, l);
    }

    // ---- per-warp ldmatrix addressing ----
    const int wid = tid >> 5, lane = tid & 31;
    const int wm = wid & 3;
    const int wn = wid >> 2;
    const int lr = lane & 7, lq = lane >> 3;

    const uint32_t aRow = (uint32_t)(wm*32 + (lq & 1)*8 + lr);
    const uint32_t aCol = (uint32_t)((lq >> 1)*8);
    const uint32_t bRow = (uint32_t)(wn*16 + (lq >> 1)*8 + lr);
    const uint32_t bCol = (uint32_t)((lq & 1)*8);

    const uint32_t aHiB = sb + SO_AHI + (aRow*KP + aCol)*2;
    const uint32_t aLoB = sb + SO_ALO + (aRow*KP + aCol)*2;
    uint32_t bHiB[2];
    #pragma unroll
    for (int s = 0; s < 2; s++)
        bHiB[s] = sb + SO_B0 + (uint32_t)s*BSLOT + (bRow*KP + bCol)*2;

    int phase = 0;
    for (int t = c; t < ntn; t += S, phase++) {
        const int slot = phase & 1;
        const int n0   = t * 64;

        // ---- store split of prefetched B tile into smem slot ----
        {
            const uint32_t bh = sb + SO_B0 + (uint32_t)slot*BSLOT;
            #pragma unroll
            for (int i = 0; i < BIT; i++) {
                int u = tid + i*512;
                if (u < 6400) {
                    int row = u / 100, c2 = u % 100;
                    uint32_t off = ((uint32_t)row*KP + (uint32_t)c2*2)*2;
                    if (FP16) {
                        STS32(bh + off, cvt2_fp(pf[i].x, pf[i].y));
                    } else {
                        uint32_t h, l;
                        split2_bf(pf[i].x, pf[i].y, h, l);
                        STS32(bh + off, h);
                        STS32(bh + B_HALF + off, l);
                    }
                }
            }
        }
        __syncthreads();

        // ---- prefetch next tile (overlaps compute below) ----
        const int tn = t + S;
        if (tn < ntn) {
            const int nn0 = tn * 64;
            #pragma unroll
            for (int i = 0; i < BIT; i++) {
                int u = tid + i*512;
                float2 v = make_float2(0.f, 0.f);
                if (u < 6400) {
                    int row = u / 100, c2 = u % 100;
                    int gr = nn0 + row;
                    if (gr < Ntot) {
                        const float* src = (gr < N1) ? (B1 + (size_t)gr*KK)
                                                     : (B2 + (size_t)(gr - N1)*KK);
                        v = *reinterpret_cast<const float2*>(src + c2*2);
                    }
                }
                pf[i] = v;
            }
        }

        // ---- compute ----
        float acc[2][2][4];
        #pragma unroll
        for (int mt = 0; mt < 2; mt++)
            #pragma unroll
            for (int ns = 0; ns < 2; ns++)
                #pragma unroll
                for (int q = 0; q < 4; q++) acc[mt][ns][q] = 0.f;

        #pragma unroll
        for (int kc = 0; kc < KC; kc++) {
            const uint32_t kOff = (uint32_t)kc * 32;
            uint32_t ah[2][4], al[2][4], bh[4], bl[4];
            #pragma unroll
            for (int mt = 0; mt < 2; mt++) {
                uint32_t o = (uint32_t)(mt*16*KP)*2 + kOff;
                ldsm4(ah[mt], aHiB + o);
                ldsm4(al[mt], aLoB + o);
            }
            ldsm4(bh, bHiB[slot] + kOff);
            if (!FP16) ldsm4(bl, bHiB[slot] + B_HALF + kOff);
            #pragma unroll
            for (int mt = 0; mt < 2; mt++)
                #pragma unroll
                for (int ns = 0; ns < 2; ns++) {
                    if (FP16) {
                        mma_fp16(acc[mt][ns], ah[mt], bh[ns*2], bh[ns*2+1]);
                        mma_fp16(acc[mt][ns], al[mt], bh[ns*2], bh[ns*2+1]);
                    } else {
                        mma_bf16(acc[mt][ns], ah[mt], bh[ns*2], bh[ns*2+1]);
                        mma_bf16(acc[mt][ns], al[mt], bh[ns*2], bh[ns*2+1]);
                        mma_bf16(acc[mt][ns], ah[mt], bl[ns*2], bl[ns*2+1]);
                    }
                }
        }

        // ---- epilogue from registers ----
        const int r0 = m0 + wm*32 + (lane >> 2);
        const int c0 = n0 + wn*16 + (lane & 3)*2;
        #pragma unroll
        for (int mt = 0; mt < 2; mt++)
            #pragma unroll
            for (int ns = 0; ns < 2; ns++) {
                int row = r0 + mt*16;
                int col = c0 + ns*8;
                if (col < Ntot) {
                    *reinterpret_cast<float2*>(C + (size_t)row*ldc + col) =
                        make_float2(acc[mt][ns][0], acc[mt][ns][1]);
                    *reinterpret_cast<float2*>(C + (size_t)(row+8)*ldc + col) =
                        make_float2(acc[mt][ns][2], acc[mt][ns][3]);
                }
            }
    }
}

// ---------------- launch ----------------
extern "C" void kernel_launch(void* const* d_in, const int* in_sizes, int n_in,
                              void* d_out, int out_size) {
    const int*   x      = (const int*)  d_in[0];
    const float* hidden = (const float*)d_in[1];
    const float* Wih0f  = (const float*)d_in[2];
    const float* Whh0f  = (const float*)d_in[3];
    const float* Wih0b  = (const float*)d_in[4];
    const float* Whh0b  = (const float*)d_in[5];
    const float* Wih1f  = (const float*)d_in[6];
    const float* Whh1f  = (const float*)d_in[7];
    const float* Wih1b  = (const float*)d_in[8];
    const float* Whh1b  = (const float*)d_in[9];
    const float* Wlin   = (const float*)d_in[10];

    float* out  = (float*)d_out;
    float* hout = out + (out_size - 4*BB*HH);

    void *p_gx0f, *p_gx0b, *p_y0, *p_gx1, *p_y1;
    cudaGetSymbolAddress(&p_gx0f, g_gx0f);
    cudaGetSymbolAddress(&p_gx0b, g_gx0b);
    cudaGetSymbolAddress(&p_y0,   g_y0);
    cudaGetSymbolAddress(&p_gx1,  g_gx1);
    cudaGetSymbolAddress(&p_y1,   g_y1);

    cudaFuncSetAttribute(pg_gemm<0>, cudaFuncAttributeMaxDynamicSharedMemorySize, SMEM3);
    cudaFuncSetAttribute(pg_gemm<1>, cudaFuncAttributeMaxDynamicSharedMemorySize, SMEM2);

    // 1. embedding gather
    gather_kernel<<<BB*TT, 2*GG>>>(x, Wih0f, Wih0b);

    // 2. GRU layer 0
    gru_kernel<<<64, 640>>>((const float*)p_gx0f, (const float*)p_gx0b, GG,
                            Whh0f, Whh0b, hidden, 0, (float*)p_y0, hout);

    // 3. fused layer-1 projections (bf16 3-pass; Ntot=600 -> 10 tiles)
    pg_gemm<0><<<dim3(5, 10), 512, SMEM3>>>((const float*)p_y0, Wih1f, Wih1b,
                                            GG, 2*GG, (float*)p_gx1, 2*GG);

    // 4. GRU layer 1 (combined gx1, stride 600)
    gru_kernel<<<64, 640>>>((const float*)p_gx1, (const float*)p_gx1 + GG, 2*GG,
                            Whh1f, Whh1b, hidden, 2, (float*)p_y1, hout);

    // 5. final projection (fp16 2-pass): 500 tiles, grid 5x29 persistent
    pg_gemm<1><<<dim3(5, 29), 512, SMEM2>>>((const float*)p_y1, Wlin, Wlin,
                                            VV, VV, out, VV);
}

// round 8
// speedup vs baseline: 2.7211x; 1.1475x over previous
#include <cuda_runtime.h>
#include <cuda_bf16.h>
#include <cuda_fp16.h>
#include <stdint.h>

#define BB   32
#define TT   20
#define HH   100
#define GG   300      // 3H
#define DD   200      // 2H
#define KK   200      // GEMM K
#define VV   32000

// ---------------- scratch (static device globals; no allocation) ----------------
__device__ float g_gx0f[BB*TT*GG];
__device__ float g_gx0b[BB*TT*GG];
__device__ float g_y0  [BB*TT*DD];
__device__ float g_gx1 [BB*TT*2*GG];   // combined fwd|bwd, row stride 600
__device__ float g_y1  [BB*TT*DD];

// ================= helpers =================
__device__ __forceinline__ uint32_t smem_u32(const void* p) {
    uint32_t a;
    asm("{ .reg .u64 t; cvta.to.shared.u64 t, %1; cvt.u32.u64 %0, t; }" : "=r"(a) : "l"(p));
    return a;
}
__device__ __forceinline__ void ldsm4(uint32_t* r, uint32_t addr) {
    asm volatile("ldmatrix.sync.aligned.m8n8.x4.shared.b16 {%0,%1,%2,%3}, [%4];"
        : "=r"(r[0]), "=r"(r[1]), "=r"(r[2]), "=r"(r[3]) : "r"(addr));
}
__device__ __forceinline__ void mma_bf16(float* c, const uint32_t* a,
                                         uint32_t b0, uint32_t b1) {
    asm volatile("mma.sync.aligned.m16n8k16.row.col.f32.bf16.bf16.f32 "
        "{%0,%1,%2,%3}, {%4,%5,%6,%7}, {%8,%9}, {%0,%1,%2,%3};"
        : "+f"(c[0]), "+f"(c[1]), "+f"(c[2]), "+f"(c[3])
        : "r"(a[0]), "r"(a[1]), "r"(a[2]), "r"(a[3]), "r"(b0), "r"(b1));
}
__device__ __forceinline__ void mma_fp16(float* c, const uint32_t* a,
                                         uint32_t b0, uint32_t b1) {
    asm volatile("mma.sync.aligned.m16n8k16.row.col.f32.f16.f16.f32 "
        "{%0,%1,%2,%3}, {%4,%5,%6,%7}, {%8,%9}, {%0,%1,%2,%3};"
        : "+f"(c[0]), "+f"(c[1]), "+f"(c[2]), "+f"(c[3])
        : "r"(a[0]), "r"(a[1]), "r"(a[2]), "r"(a[3]), "r"(b0), "r"(b1));
}
__device__ __forceinline__ void split2_bf(float a, float b, uint32_t& hi, uint32_t& lo) {
    __nv_bfloat16 ha = __float2bfloat16(a), hb = __float2bfloat16(b);
    __nv_bfloat16 la = __float2bfloat16(a - __bfloat162float(ha));
    __nv_bfloat16 lb = __float2bfloat16(b - __bfloat162float(hb));
    __nv_bfloat162 h2 = __halves2bfloat162(ha, hb), l2 = __halves2bfloat162(la, lb);
    hi = *reinterpret_cast<uint32_t*>(&h2);
    lo = *reinterpret_cast<uint32_t*>(&l2);
}
__device__ __forceinline__ uint32_t cvt2_fp(float a, float b) {
    __half2 h2 = __floats2half2_rn(a, b);
    return *reinterpret_cast<uint32_t*>(&h2);
}
__device__ __forceinline__ unsigned long long pack_f32x2(float lo, float hi) {
    unsigned long long r;
    asm("mov.b64 %0, {%1, %2};" : "=l"(r) : "f"(lo), "f"(hi));
    return r;
}
__device__ __forceinline__ unsigned long long fma_f32x2(
    unsigned long long a, unsigned long long b, unsigned long long c) {
    unsigned long long d;
    asm("fma.rn.f32x2 %0, %1, %2, %3;" : "=l"(d) : "l"(a), "l"(b), "l"(c));
    return d;
}
__device__ __forceinline__ void unpack_f32x2(unsigned long long v, float& lo, float& hi) {
    asm("mov.b64 {%0, %1}, %2;" : "=f"(lo), "=f"(hi) : "l"(v));
}
#define STS32(addr, v) \
    asm volatile("st.shared.b32 [%0], %1;" :: "r"(addr), "r"(v) : "memory")

// ---------------- embedding gather --------------------------------
__global__ void gather_kernel(const int* __restrict__ x,
                              const float* __restrict__ Wf,
                              const float* __restrict__ Wb) {
    int tok = blockIdx.x;
    int v   = x[tok];
    int tid = threadIdx.x;
    if (tid < GG) g_gx0f[tok*GG + tid]      = Wf[tid*VV + v];
    else          g_gx0b[tok*GG + (tid-GG)] = Wb[(tid-GG)*VV + v];
}

// ---------------- GRU: gates-in-warp, double-buffered h, 1 barrier/step -----
// 640 threads = 20 warps; warp w owns hidden units 5w..5w+4. Lane = 6i+2g+s:
// gate g (0=r,1=z,2=n), half s of the 100-wide dot. Pair-reduce shfl_xor(1),
// then shfl_down(2)/(4) deliver hz,hn to the r-lane which does the full
// activation and writes h (to the other h buffer) + y. One barrier per step.
__global__ __launch_bounds__(640) void gru_kernel(
    const float* __restrict__ gxf, const float* __restrict__ gxb, int ldg_,
    const float* __restrict__ Whhf, const float* __restrict__ Whhb,
    const float* __restrict__ hidden, int hid_base,
    float* __restrict__ y, float* __restrict__ hout)
{
    int dir = blockIdx.x >> 5;
    int b   = blockIdx.x & 31;
    const float* gx  = dir ? gxb  : gxf;
    const float* Whh = dir ? Whhb : Whhf;
    int tid  = threadIdx.x;
    int wid  = tid >> 5, lane = tid & 31;
    int i    = lane / 6;  if (i > 4) i = 4;     // clamp lanes 30,31
    int rr   = lane % 6;
    int g    = rr >> 1;                          // gate 0..2
    int s    = rr & 1;                           // half 0/1
    int u    = wid * 5 + i;                      // hidden unit 0..99
    bool store_lane = (lane % 6 == 0) && (lane < 30);

    __shared__ __align__(16) float h_s[2][104];     // double buffer, 4 pad
    __shared__ __align__(8)  float gx_all[TT*GG + 8];

    // ---- preload all gx rows (float2, coalesced, full MLP) ----
    for (int q = tid; q < TT*(GG/2); q += 640) {
        int row = q / (GG/2);
        int c2  = q - row*(GG/2);
        *reinterpret_cast<float2*>(gx_all + row*GG + c2*2) =
            *reinterpret_cast<const float2*>(gx + (size_t)(b*TT + row)*ldg_ + c2*2);
    }

    // ---- weights (row = g*100+u, cols s*52..) into 26 packed f32x2 ----
    const int base = s * 52;
    const int wcnt = s ? 48 : 52;
    unsigned long long w2[26];
    {
        const float* wrow = Whh + (g*HH + u)*HH + base;
        #pragma unroll
        for (int k = 0; k < 26; k++) {
            float wa = (2*k   < wcnt) ? wrow[2*k]   : 0.f;
            float wb = (2*k+1 < wcnt) ? wrow[2*k+1] : 0.f;
            w2[k] = pack_f32x2(wa, wb);
        }
    }

    if (tid < HH) h_s[0][tid] = hidden[(hid_base + dir)*BB*HH + b*HH + tid];
    if (tid < 8) { h_s[0][100 + (tid&3)] = 0.f; h_s[1][100 + (tid&3)] = 0.f; }
    __syncthreads();

    const uint32_t hbase0 = smem_u32(&h_s[0][0]) + (uint32_t)base*4;
    const uint32_t hbase1 = smem_u32(&h_s[1][0]) + (uint32_t)base*4;

    for (int t = 0; t < TT; t++) {
        int tt = dir ? (TT-1-t) : t;
        const float* gxr = gx_all + tt*GG;
        const int cur = t & 1;
        const uint32_t hb = cur ? hbase1 : hbase0;

        unsigned long long acc0 = 0ull, acc1 = 0ull;
        #pragma unroll
        for (int kk = 0; kk < 13; kk++) {
            unsigned long long p, q;
            asm volatile("ld.shared.v2.u64 {%0,%1}, [%2];"
                : "=l"(p), "=l"(q) : "r"(hb + (uint32_t)kk*16));
            acc0 = fma_f32x2(w2[2*kk],   p, acc0);
            acc1 = fma_f32x2(w2[2*kk+1], q, acc1);
        }
        float a0, a1, a2, a3;
        unpack_f32x2(acc0, a0, a1);
        unpack_f32x2(acc1, a2, a3);
        float dot = (a0 + a1) + (a2 + a3);
        dot += __shfl_xor_sync(0xffffffffu, dot, 1);

        // gate exchange within warp (r-lane receives z,n dots)
        float hz = __shfl_down_sync(0xffffffffu, dot, 2);
        float hn = __shfl_down_sync(0xffffffffu, dot, 4);

        // activation (all lanes compute; only r-lanes store)
        float xr = gxr[u], xz = gxr[HH+u], xn = gxr[2*HH+u];
        float r  = __fdividef(1.f, 1.f + __expf(-(xr + dot)));
        float z  = __fdividef(1.f, 1.f + __expf(-(xz + hz)));
        float uu = xn + r*hn;
        float nn = __fdividef(2.f, 1.f + __expf(-2.f*uu)) - 1.f;   // tanh
        float ho = h_s[cur][u];
        float hv = (1.f - z)*nn + z*ho;
        if (store_lane) {
            h_s[cur ^ 1][u] = hv;
            y[(b*TT + tt)*DD + dir*HH + u] = hv;
        }
        __syncthreads();
    }
    if (tid < HH) hout[(hid_base + dir)*BB*HH + b*HH + tid] = h_s[0][tid];
}

// ================= reg-prefetch split GEMM (mma.sync), templated ============
// ONEPASS=0: bf16 3-pass (A hi/lo, B hi/lo) — err ~1e-5. Projections.
// ONEPASS=1: fp16 1-pass (A and B rounded)  — err ~3e-4. Final GEMM.
#define KP   216
#define KC   13
#define A_BY     55296             // 128*216*2 per copy
#define B_HALF   27648
#define SMEM3    221184            // Ahi+Alo + 2 B slots of 2 halves
#define SMEM1    110592            // Ahi + 2 B slots of 1 half
#define BIT  13                    // B tile iterations (ceil(6400/512))

template<int ONEPASS>
__global__ __launch_bounds__(512, 1) void pg_gemm(
    const float* __restrict__ A,
    const float* __restrict__ B1, const float* __restrict__ B2, int N1,
    int Ntot, float* __restrict__ C, int ldc)
{
    constexpr uint32_t BSLOT = ONEPASS ? 27648 : 55296;
    constexpr uint32_t SO_B0v = ONEPASS ? A_BY : 2*A_BY;
    extern __shared__ __align__(16) unsigned char dsm[];
    const uint32_t sb = smem_u32(dsm);
    const int tid = threadIdx.x;
    const int m0  = blockIdx.x * 128;
    const int c   = blockIdx.y;
    const int S   = gridDim.y;
    const int ntn = (Ntot + 63) / 64;
    if (c >= ntn) return;

    // ---- zero K pads (cols 200..207) ----
    {
        int row = tid >> 2, wd = tid & 3;
        uint32_t off = ((uint32_t)row*KP + 200)*2 + (uint32_t)wd*4;
        STS32(sb + off, 0u);
        if (!ONEPASS) STS32(sb + A_BY + off, 0u);
        const int nreg = ONEPASS ? 2 : 4;
        for (int q = tid; q < nreg*256; q += 512) {
            int reg = q >> 8;
            int j   = q & 255;
            int br  = j >> 2, bw = j & 3;
            uint32_t bbase = ONEPASS
                ? sb + SO_B0v + (uint32_t)reg*BSLOT
                : sb + SO_B0v + (uint32_t)(reg >> 1)*BSLOT + (uint32_t)(reg & 1)*B_HALF;
            STS32(bbase + ((uint32_t)br*KP + 200)*2 + (uint32_t)bw*4, 0u);
        }
    }

    // ---- prologue prefetch of first B tile ----
    float2 pf[BIT];
    {
        const int n0 = c * 64;
        #pragma unroll
        for (int q = 0; q < BIT; q++) {
            int u = tid + q*512;
            float2 v = make_float2(0.f, 0.f);
            if (u < 6400) {
                int row = u / 100, c2 = u % 100;
                int gr = n0 + row;
                if (gr < Ntot) {
                    const float* src = (gr < N1) ? (B1 + (size_t)gr*KK)
                                                 : (B2 + (size_t)(gr - N1)*KK);
                    v = *reinterpret_cast<const float2*>(src + c2*2);
                }
            }
            pf[q] = v;
        }
    }

    // ---- load A m-block (once) ----
    #pragma unroll
    for (int q = 0; q < 25; q++) {
        int u = tid + q*512;
        int row = u / 100, c2 = u % 100;
        float2 v = *reinterpret_cast<const float2*>(A + (size_t)(m0+row)*KK + c2*2);
        uint32_t off = ((uint32_t)row*KP + (uint32_t)c2*2)*2;
        if (ONEPASS) {
            STS32(sb + off, cvt2_fp(v.x, v.y));
        } else {
            uint32_t h, l;
            split2_bf(v.x, v.y, h, l);
            STS32(sb + off, h);
            STS32(sb + A_BY + off, l);
        }
    }

    // ---- per-warp ldmatrix addressing ----
    const int wid = tid >> 5, lane = tid & 31;
    const int wm = wid & 3;
    const int wn = wid >> 2;
    const int lr = lane & 7, lq = lane >> 3;

    const uint32_t aRow = (uint32_t)(wm*32 + (lq & 1)*8 + lr);
    const uint32_t aCol = (uint32_t)((lq >> 1)*8);
    const uint32_t bRow = (uint32_t)(wn*16 + (lq >> 1)*8 + lr);
    const uint32_t bCol = (uint32_t)((lq & 1)*8);

    const uint32_t aHiB = sb + (aRow*KP + aCol)*2;
    const uint32_t aLoB = aHiB + A_BY;
    uint32_t bHiB[2];
    #pragma unroll
    for (int s2 = 0; s2 < 2; s2++)
        bHiB[s2] = sb + SO_B0v + (uint32_t)s2*BSLOT + (bRow*KP + bCol)*2;

    int phase = 0;
    for (int t = c; t < ntn; t += S, phase++) {
        const int slot = phase & 1;
        const int n0   = t * 64;

        // ---- store prefetched B tile into smem slot ----
        {
            const uint32_t bh = sb + SO_B0v + (uint32_t)slot*BSLOT;
            #pragma unroll
            for (int q = 0; q < BIT; q++) {
                int u = tid + q*512;
                if (u < 6400) {
                    int row = u / 100, c2 = u % 100;
                    uint32_t off = ((uint32_t)row*KP + (uint32_t)c2*2)*2;
                    if (ONEPASS) {
                        STS32(bh + off, cvt2_fp(pf[q].x, pf[q].y));
                    } else {
                        uint32_t h, l;
                        split2_bf(pf[q].x, pf[q].y, h, l);
                        STS32(bh + off, h);
                        STS32(bh + B_HALF + off, l);
                    }
                }
            }
        }
        __syncthreads();

        // ---- prefetch next tile (overlaps compute) ----
        const int tn = t + S;
        if (tn < ntn) {
            const int nn0 = tn * 64;
            #pragma unroll
            for (int q = 0; q < BIT; q++) {
                int u = tid + q*512;
                float2 v = make_float2(0.f, 0.f);
                if (u < 6400) {
                    int row = u / 100, c2 = u % 100;
                    int gr = nn0 + row;
                    if (gr < Ntot) {
                        const float* src = (gr < N1) ? (B1 + (size_t)gr*KK)
                                                     : (B2 + (size_t)(gr - N1)*KK);
                        v = *reinterpret_cast<const float2*>(src + c2*2);
                    }
                }
                pf[q] = v;
            }
        }

        // ---- compute ----
        float acc[2][2][4];
        #pragma unroll
        for (int mt = 0; mt < 2; mt++)
            #pragma unroll
            for (int ns = 0; ns < 2; ns++)
                #pragma unroll
                for (int q = 0; q < 4; q++) acc[mt][ns][q] = 0.f;

        #pragma unroll
        for (int kc = 0; kc < KC; kc++) {
            const uint32_t kOff = (uint32_t)kc * 32;
            uint32_t ah[2][4], al[2][4], bh[4], bl[4];
            #pragma unroll
            for (int mt = 0; mt < 2; mt++) {
                uint32_t o = (uint32_t)(mt*16*KP)*2 + kOff;
                ldsm4(ah[mt], aHiB + o);
                if (!ONEPASS) ldsm4(al[mt], aLoB + o);
            }
            ldsm4(bh, bHiB[slot] + kOff);
            if (!ONEPASS) ldsm4(bl, bHiB[slot] + B_HALF + kOff);
            #pragma unroll
            for (int mt = 0; mt < 2; mt++)
                #pragma unroll
                for (int ns = 0; ns < 2; ns++) {
                    if (ONEPASS) {
                        mma_fp16(acc[mt][ns], ah[mt], bh[ns*2], bh[ns*2+1]);
                    } else {
                        mma_bf16(acc[mt][ns], ah[mt], bh[ns*2], bh[ns*2+1]);
                        mma_bf16(acc[mt][ns], al[mt], bh[ns*2], bh[ns*2+1]);
                        mma_bf16(acc[mt][ns], ah[mt], bl[ns*2], bl[ns*2+1]);
                    }
                }
        }

        // ---- epilogue from registers ----
        const int r0 = m0 + wm*32 + (lane >> 2);
        const int c0 = n0 + wn*16 + (lane & 3)*2;
        #pragma unroll
        for (int mt = 0; mt < 2; mt++)
            #pragma unroll
            for (int ns = 0; ns < 2; ns++) {
                int row = r0 + mt*16;
                int col = c0 + ns*8;
                if (col < Ntot) {
                    *reinterpret_cast<float2*>(C + (size_t)row*ldc + col) =
                        make_float2(acc[mt][ns][0], acc[mt][ns][1]);
                    *reinterpret_cast<float2*>(C + (size_t)(row+8)*ldc + col) =
                        make_float2(acc[mt][ns][2], acc[mt][ns][3]);
                }
            }
    }
}

// ---------------- launch ----------------
extern "C" void kernel_launch(void* const* d_in, const int* in_sizes, int n_in,
                              void* d_out, int out_size) {
    const int*   x      = (const int*)  d_in[0];
    const float* hidden = (const float*)d_in[1];
    const float* Wih0f  = (const float*)d_in[2];
    const float* Whh0f  = (const float*)d_in[3];
    const float* Wih0b  = (const float*)d_in[4];
    const float* Whh0b  = (const float*)d_in[5];
    const float* Wih1f  = (const float*)d_in[6];
    const float* Whh1f  = (const float*)d_in[7];
    const float* Wih1b  = (const float*)d_in[8];
    const float* Whh1b  = (const float*)d_in[9];
    const float* Wlin   = (const float*)d_in[10];

    float* out  = (float*)d_out;
    float* hout = out + (out_size - 4*BB*HH);

    void *p_gx0f, *p_gx0b, *p_y0, *p_gx1, *p_y1;
    cudaGetSymbolAddress(&p_gx0f, g_gx0f);
    cudaGetSymbolAddress(&p_gx0b, g_gx0b);
    cudaGetSymbolAddress(&p_y0,   g_y0);
    cudaGetSymbolAddress(&p_gx1,  g_gx1);
    cudaGetSymbolAddress(&p_y1,   g_y1);

    cudaFuncSetAttribute(pg_gemm<0>, cudaFuncAttributeMaxDynamicSharedMemorySize, SMEM3);
    cudaFuncSetAttribute(pg_gemm<1>, cudaFuncAttributeMaxDynamicSharedMemorySize, SMEM1);

    // 1. embedding gather
    gather_kernel<<<BB*TT, 2*GG>>>(x, Wih0f, Wih0b);

    // 2. GRU layer 0
    gru_kernel<<<64, 640>>>((const float*)p_gx0f, (const float*)p_gx0b, GG,
                            Whh0f, Whh0b, hidden, 0, (float*)p_y0, hout);

    // 3. fused layer-1 projections (bf16 3-pass; Ntot=600 -> 10 tiles)
    pg_gemm<0><<<dim3(5, 10), 512, SMEM3>>>((const float*)p_y0, Wih1f, Wih1b,
                                            GG, 2*GG, (float*)p_gx1, 2*GG);

    // 4. GRU layer 1 (combined gx1, stride 600)
    gru_kernel<<<64, 640>>>((const float*)p_gx1, (const float*)p_gx1 + GG, 2*GG,
                            Whh1f, Whh1b, hidden, 2, (float*)p_y1, hout);

    // 5. final projection (fp16 1-pass): 2500 tiles, grid 5x29 persistent
    pg_gemm<1><<<dim3(5, 29), 512, SMEM1>>>((const float*)p_y1, Wlin, Wlin,
                                            VV, VV, out, VV);
}

// round 9
// speedup vs baseline: 2.9120x; 1.0702x over previous
#include <cuda_runtime.h>
#include <cuda_bf16.h>
#include <cuda_fp16.h>
#include <stdint.h>

#define BB   32
#define TT   20
#define HH   100
#define GG   300      // 3H
#define DD   200      // 2H
#define KK   200      // GEMM K
#define VV   32000

// ---------------- scratch (static device globals; no allocation) ----------------
__device__ float g_gx0f[BB*TT*GG];
__device__ float g_gx0b[BB*TT*GG];
__device__ float g_y0  [BB*TT*DD];
__device__ float g_gx1 [BB*TT*2*GG];   // combined fwd|bwd, row stride 600
__device__ float g_y1  [BB*TT*DD];
__device__ __half g_wl16[VV*KK];       // pre-converted W_lin (12.8 MB)

// ================= helpers =================
__device__ __forceinline__ uint32_t smem_u32(const void* p) {
    uint32_t a;
    asm("{ .reg .u64 t; cvta.to.shared.u64 t, %1; cvt.u32.u64 %0, t; }" : "=r"(a) : "l"(p));
    return a;
}
__device__ __forceinline__ void ldsm4(uint32_t* r, uint32_t addr) {
    asm volatile("ldmatrix.sync.aligned.m8n8.x4.shared.b16 {%0,%1,%2,%3}, [%4];"
        : "=r"(r[0]), "=r"(r[1]), "=r"(r[2]), "=r"(r[3]) : "r"(addr));
}
__device__ __forceinline__ void mma_bf16(float* c, const uint32_t* a,
                                         uint32_t b0, uint32_t b1) {
    asm volatile("mma.sync.aligned.m16n8k16.row.col.f32.bf16.bf16.f32 "
        "{%0,%1,%2,%3}, {%4,%5,%6,%7}, {%8,%9}, {%0,%1,%2,%3};"
        : "+f"(c[0]), "+f"(c[1]), "+f"(c[2]), "+f"(c[3])
        : "r"(a[0]), "r"(a[1]), "r"(a[2]), "r"(a[3]), "r"(b0), "r"(b1));
}
__device__ __forceinline__ void mma_fp16(float* c, const uint32_t* a,
                                         uint32_t b0, uint32_t b1) {
    asm volatile("mma.sync.aligned.m16n8k16.row.col.f32.f16.f16.f32 "
        "{%0,%1,%2,%3}, {%4,%5,%6,%7}, {%8,%9}, {%0,%1,%2,%3};"
        : "+f"(c[0]), "+f"(c[1]), "+f"(c[2]), "+f"(c[3])
        : "r"(a[0]), "r"(a[1]), "r"(a[2]), "r"(a[3]), "r"(b0), "r"(b1));
}
__device__ __forceinline__ void split2_bf(float a, float b, uint32_t& hi, uint32_t& lo) {
    __nv_bfloat16 ha = __float2bfloat16(a), hb = __float2bfloat16(b);
    __nv_bfloat16 la = __float2bfloat16(a - __bfloat162float(ha));
    __nv_bfloat16 lb = __float2bfloat16(b - __bfloat162float(hb));
    __nv_bfloat162 h2 = __halves2bfloat162(ha, hb), l2 = __halves2bfloat162(la, lb);
    hi = *reinterpret_cast<uint32_t*>(&h2);
    lo = *reinterpret_cast<uint32_t*>(&l2);
}
__device__ __forceinline__ uint32_t cvt2_fp(float a, float b) {
    __half2 h2 = __floats2half2_rn(a, b);
    return *reinterpret_cast<uint32_t*>(&h2);
}
__device__ __forceinline__ unsigned long long pack_f32x2(float lo, float hi) {
    unsigned long long r;
    asm("mov.b64 %0, {%1, %2};" : "=l"(r) : "f"(lo), "f"(hi));
    return r;
}
__device__ __forceinline__ unsigned long long fma_f32x2(
    unsigned long long a, unsigned long long b, unsigned long long c) {
    unsigned long long d;
    asm("fma.rn.f32x2 %0, %1, %2, %3;" : "=l"(d) : "l"(a), "l"(b), "l"(c));
    return d;
}
__device__ __forceinline__ void unpack_f32x2(unsigned long long v, float& lo, float& hi) {
    asm("mov.b64 {%0, %1}, %2;" : "=f"(lo), "=f"(hi) : "l"(v));
}
#define STS32(addr, v) \
    asm volatile("st.shared.b32 [%0], %1;" :: "r"(addr), "r"(v) : "memory")
#define CP_ASYNC16(saddr, gaddr) \
    asm volatile("cp.async.cg.shared.global [%0], [%1], 16;" \
        :: "r"(saddr), "l"(gaddr) : "memory")
#define CP_COMMIT() asm volatile("cp.async.commit_group;" ::: "memory")
#define CP_WAIT1()  asm volatile("cp.async.wait_group 1;"  ::: "memory")

// ---------------- W_lin fp32 -> fp16 convert (once per run) -----------------
__global__ void convert_kernel(const float* __restrict__ W) {
    int i = (blockIdx.x * 256 + threadIdx.x) * 4;   // 6.4M elems / 4
    float4 v = *reinterpret_cast<const float4*>(W + i);
    __half2* o = reinterpret_cast<__half2*>(g_wl16 + i);
    o[0] = __floats2half2_rn(v.x, v.y);
    o[1] = __floats2half2_rn(v.z, v.w);
}

// ---------------- embedding gather --------------------------------
__global__ void gather_kernel(const int* __restrict__ x,
                              const float* __restrict__ Wf,
                              const float* __restrict__ Wb) {
    int tok = blockIdx.x;
    int v   = x[tok];
    int tid = threadIdx.x;
    if (tid < GG) g_gx0f[tok*GG + tid]      = Wf[tid*VV + v];
    else          g_gx0b[tok*GG + (tid-GG)] = Wb[(tid-GG)*VV + v];
}

// ---------------- GRU: gates-in-warp, double-buffered h, 1 barrier/step -----
__global__ __launch_bounds__(640) void gru_kernel(
    const float* __restrict__ gxf, const float* __restrict__ gxb, int ldg_,
    const float* __restrict__ Whhf, const float* __restrict__ Whhb,
    const float* __restrict__ hidden, int hid_base,
    float* __restrict__ y, float* __restrict__ hout)
{
    int dir = blockIdx.x >> 5;
    int b   = blockIdx.x & 31;
    const float* gx  = dir ? gxb  : gxf;
    const float* Whh = dir ? Whhb : Whhf;
    int tid  = threadIdx.x;
    int wid  = tid >> 5, lane = tid & 31;
    int i    = lane / 6;  if (i > 4) i = 4;
    int rr   = lane % 6;
    int g    = rr >> 1;
    int s    = rr & 1;
    int u    = wid * 5 + i;
    bool store_lane = (lane % 6 == 0) && (lane < 30);

    __shared__ __align__(16) float h_s[2][104];
    __shared__ __align__(8)  float gx_all[TT*GG + 8];

    for (int q = tid; q < TT*(GG/2); q += 640) {
        int row = q / (GG/2);
        int c2  = q - row*(GG/2);
        *reinterpret_cast<float2*>(gx_all + row*GG + c2*2) =
            *reinterpret_cast<const float2*>(gx + (size_t)(b*TT + row)*ldg_ + c2*2);
    }

    const int base = s * 52;
    const int wcnt = s ? 48 : 52;
    unsigned long long w2[26];
    {
        const float* wrow = Whh + (g*HH + u)*HH + base;
        #pragma unroll
        for (int k = 0; k < 26; k++) {
            float wa = (2*k   < wcnt) ? wrow[2*k]   : 0.f;
            float wb = (2*k+1 < wcnt) ? wrow[2*k+1] : 0.f;
            w2[k] = pack_f32x2(wa, wb);
        }
    }

    if (tid < HH) h_s[0][tid] = hidden[(hid_base + dir)*BB*HH + b*HH + tid];
    if (tid < 8) { h_s[0][100 + (tid&3)] = 0.f; h_s[1][100 + (tid&3)] = 0.f; }
    __syncthreads();

    const uint32_t hbase0 = smem_u32(&h_s[0][0]) + (uint32_t)base*4;
    const uint32_t hbase1 = smem_u32(&h_s[1][0]) + (uint32_t)base*4;

    for (int t = 0; t < TT; t++) {
        int tt = dir ? (TT-1-t) : t;
        const float* gxr = gx_all + tt*GG;
        const int cur = t & 1;
        const uint32_t hb = cur ? hbase1 : hbase0;

        // pre-issue gx loads (independent of the dot chain)
        float xr = gxr[u], xz = gxr[HH+u], xn = gxr[2*HH+u];
        float ho = h_s[cur][u];

        // software-pipelined dot (load kk+1 while FMA-ing kk)
        unsigned long long acc0 = 0ull, acc1 = 0ull;
        unsigned long long p0, q0, p1, q1;
        asm volatile("ld.shared.v2.u64 {%0,%1}, [%2];" : "=l"(p0), "=l"(q0) : "r"(hb));
        #pragma unroll
        for (int kk = 0; kk < 13; kk++) {
            if (kk < 12) {
                asm volatile("ld.shared.v2.u64 {%0,%1}, [%2];"
                    : "=l"(p1), "=l"(q1) : "r"(hb + (uint32_t)(kk+1)*16));
            }
            acc0 = fma_f32x2(w2[2*kk],   p0, acc0);
            acc1 = fma_f32x2(w2[2*kk+1], q0, acc1);
            p0 = p1; q0 = q1;
        }
        float a0, a1, a2, a3;
        unpack_f32x2(acc0, a0, a1);
        unpack_f32x2(acc1, a2, a3);
        float dot = (a0 + a1) + (a2 + a3);
        dot += __shfl_xor_sync(0xffffffffu, dot, 1);

        float hz = __shfl_down_sync(0xffffffffu, dot, 2);
        float hn = __shfl_down_sync(0xffffffffu, dot, 4);

        float r  = __fdividef(1.f, 1.f + __expf(-(xr + dot)));
        float z  = __fdividef(1.f, 1.f + __expf(-(xz + hz)));
        float uu = xn + r*hn;
        float nn = __fdividef(2.f, 1.f + __expf(-2.f*uu)) - 1.f;
        float hv = (1.f - z)*nn + z*ho;
        if (store_lane) {
            h_s[cur ^ 1][u] = hv;
            y[(b*TT + tt)*DD + dir*HH + u] = hv;
        }
        __syncthreads();
    }
    if (tid < HH) hout[(hid_base + dir)*BB*HH + b*HH + tid] = h_s[0][tid];
}

// ================= bf16 3-pass GEMM (projections only) =======================
#define KP   216
#define KC   13
#define A_BY     55296
#define B_HALF   27648
#define SMEM3    221184
#define BIT  13

__global__ __launch_bounds__(512, 1) void pg_gemm(
    const float* __restrict__ A,
    const float* __restrict__ B1, const float* __restrict__ B2, int N1,
    int Ntot, float* __restrict__ C, int ldc)
{
    constexpr uint32_t BSLOT = 55296;
    constexpr uint32_t SO_B0v = 2*A_BY;
    extern __shared__ __align__(16) unsigned char dsm[];
    const uint32_t sb = smem_u32(dsm);
    const int tid = threadIdx.x;
    const int m0  = blockIdx.x * 128;
    const int c   = blockIdx.y;
    const int S   = gridDim.y;
    const int ntn = (Ntot + 63) / 64;
    if (c >= ntn) return;

    {
        int row = tid >> 2, wd = tid & 3;
        uint32_t off = ((uint32_t)row*KP + 200)*2 + (uint32_t)wd*4;
        STS32(sb + off, 0u);
        STS32(sb + A_BY + off, 0u);
        for (int q = tid; q < 4*256; q += 512) {
            int reg = q >> 8;
            int j   = q & 255;
            int br  = j >> 2, bw = j & 3;
            uint32_t bbase = sb + SO_B0v + (uint32_t)(reg >> 1)*BSLOT + (uint32_t)(reg & 1)*B_HALF;
            STS32(bbase + ((uint32_t)br*KP + 200)*2 + (uint32_t)bw*4, 0u);
        }
    }

    float2 pf[BIT];
    {
        const int n0 = c * 64;
        #pragma unroll
        for (int q = 0; q < BIT; q++) {
            int u = tid + q*512;
            float2 v = make_float2(0.f, 0.f);
            if (u < 6400) {
                int row = u / 100, c2 = u % 100;
                int gr = n0 + row;
                if (gr < Ntot) {
                    const float* src = (gr < N1) ? (B1 + (size_t)gr*KK)
                                                 : (B2 + (size_t)(gr - N1)*KK);
                    v = *reinterpret_cast<const float2*>(src + c2*2);
                }
            }
            pf[q] = v;
        }
    }

    #pragma unroll
    for (int q = 0; q < 25; q++) {
        int u = tid + q*512;
        int row = u / 100, c2 = u % 100;
        float2 v = *reinterpret_cast<const float2*>(A + (size_t)(m0+row)*KK + c2*2);
        uint32_t h, l;
        split2_bf(v.x, v.y, h, l);
        uint32_t off = ((uint32_t)row*KP + (uint32_t)c2*2)*2;
        STS32(sb + off, h);
        STS32(sb + A_BY + off, l);
    }

    const int wid = tid >> 5, lane = tid & 31;
    const int wm = wid & 3;
    const int wn = wid >> 2;
    const int lr = lane & 7, lq = lane >> 3;

    const uint32_t aRow = (uint32_t)(wm*32 + (lq & 1)*8 + lr);
    const uint32_t aCol = (uint32_t)((lq >> 1)*8);
    const uint32_t bRow = (uint32_t)(wn*16 + (lq >> 1)*8 + lr);
    const uint32_t bCol = (uint32_t)((lq & 1)*8);

    const uint32_t aHiB = sb + (aRow*KP + aCol)*2;
    const uint32_t aLoB = aHiB + A_BY;
    uint32_t bHiB[2];
    #pragma unroll
    for (int s2 = 0; s2 < 2; s2++)
        bHiB[s2] = sb + SO_B0v + (uint32_t)s2*BSLOT + (bRow*KP + bCol)*2;

    int phase = 0;
    for (int t = c; t < ntn; t += S, phase++) {
        const int slot = phase & 1;
        const int n0   = t * 64;

        {
            const uint32_t bh = sb + SO_B0v + (uint32_t)slot*BSLOT;
            #pragma unroll
            for (int q = 0; q < BIT; q++) {
                int u = tid + q*512;
                if (u < 6400) {
                    int row = u / 100, c2 = u % 100;
                    uint32_t off = ((uint32_t)row*KP + (uint32_t)c2*2)*2;
                    uint32_t h, l;
                    split2_bf(pf[q].x, pf[q].y, h, l);
                    STS32(bh + off, h);
                    STS32(bh + B_HALF + off, l);
                }
            }
        }
        __syncthreads();

        const int tn = t + S;
        if (tn < ntn) {
            const int nn0 = tn * 64;
            #pragma unroll
            for (int q = 0; q < BIT; q++) {
                int u = tid + q*512;
                float2 v = make_float2(0.f, 0.f);
                if (u < 6400) {
                    int row = u / 100, c2 = u % 100;
                    int gr = nn0 + row;
                    if (gr < Ntot) {
                        const float* src = (gr < N1) ? (B1 + (size_t)gr*KK)
                                                     : (B2 + (size_t)(gr - N1)*KK);
                        v = *reinterpret_cast<const float2*>(src + c2*2);
                    }
                }
                pf[q] = v;
            }
        }

        float acc[2][2][4];
        #pragma unroll
        for (int mt = 0; mt < 2; mt++)
            #pragma unroll
            for (int ns = 0; ns < 2; ns++)
                #pragma unroll
                for (int q = 0; q < 4; q++) acc[mt][ns][q] = 0.f;

        #pragma unroll
        for (int kc = 0; kc < KC; kc++) {
            const uint32_t kOff = (uint32_t)kc * 32;
            uint32_t ah[2][4], al[2][4], bh[4], bl[4];
            #pragma unroll
            for (int mt = 0; mt < 2; mt++) {
                uint32_t o = (uint32_t)(mt*16*KP)*2 + kOff;
                ldsm4(ah[mt], aHiB + o);
                ldsm4(al[mt], aLoB + o);
            }
            ldsm4(bh, bHiB[slot] + kOff);
            ldsm4(bl, bHiB[slot] + B_HALF + kOff);
            #pragma unroll
            for (int mt = 0; mt < 2; mt++)
                #pragma unroll
                for (int ns = 0; ns < 2; ns++) {
                    mma_bf16(acc[mt][ns], ah[mt], bh[ns*2], bh[ns*2+1]);
                    mma_bf16(acc[mt][ns], al[mt], bh[ns*2], bh[ns*2+1]);
                    mma_bf16(acc[mt][ns], ah[mt], bl[ns*2], bl[ns*2+1]);
                }
        }

        const int r0 = m0 + wm*32 + (lane >> 2);
        const int c0 = n0 + wn*16 + (lane & 3)*2;
        #pragma unroll
        for (int mt = 0; mt < 2; mt++)
            #pragma unroll
            for (int ns = 0; ns < 2; ns++) {
                int row = r0 + mt*16;
                int col = c0 + ns*8;
                if (col < Ntot) {
                    *reinterpret_cast<float2*>(C + (size_t)row*ldc + col) =
                        make_float2(acc[mt][ns][0], acc[mt][ns][1]);
                    *reinterpret_cast<float2*>(C + (size_t)(row+8)*ldc + col) =
                        make_float2(acc[mt][ns][2], acc[mt][ns][3]);
                }
            }
    }
}

// ================= final GEMM: fp16, cp.async 3-stage, 128x128 tiles =========
// C[640,32000] = A[640,200] * Wl16[32000,200]^T. B pre-converted fp16.
#define WG_SMEM 221184     // A (55296) + 3 B stages (55296 each)

__global__ __launch_bounds__(512, 1) void wl_gemm(
    const float* __restrict__ A, const __half* __restrict__ Bw,
    float* __restrict__ C)
{
    extern __shared__ __align__(16) unsigned char dsm[];
    const uint32_t sb = smem_u32(dsm);
    const int tid = threadIdx.x;
    const int m0  = blockIdx.x * 128;
    const int c   = blockIdx.y;
    const int S   = gridDim.y;
    const int ntn = VV / 128;          // 250

    // ---- zero K pads (cols 200..215) of A + 3 B stages ----
    for (int q = tid; q < 4*128*8; q += 512) {    // 4 regions x 128 rows x 8 words
        int reg = q >> 10;
        int j   = q & 1023;
        int row = j >> 3, wd = j & 7;
        uint32_t base = sb + (uint32_t)reg*A_BY;   // region 0 = A, 1..3 = B stages
        STS32(base + ((uint32_t)row*KP + 200)*2 + (uint32_t)wd*4, 0u);
    }

    // ---- load + convert A m-block (once) ----
    #pragma unroll
    for (int q = 0; q < 25; q++) {
        int u = tid + q*512;
        int row = u / 100, c2 = u % 100;
        float2 v = *reinterpret_cast<const float2*>(A + (size_t)(m0+row)*KK + c2*2);
        STS32(sb + ((uint32_t)row*KP + (uint32_t)c2*2)*2, cvt2_fp(v.x, v.y));
    }

    // ---- cp.async issue helper: tile n-index tn into stage st ----
    auto issue = [&](int tn, int st) {
        const int n0 = tn * 128;
        const uint32_t bs = sb + (uint32_t)(1 + st)*A_BY;
        #pragma unroll
        for (int q = 0; q < 7; q++) {              // 3200 chunks / 512
            int u = tid + q*512;
            if (u < 3200) {
                int row = u / 25, ch = u % 25;
                const __half* gp = Bw + (size_t)(n0 + row)*KK + ch*8;
                CP_ASYNC16(bs + (uint32_t)row*(KP*2) + (uint32_t)ch*16,
                           (const void*)gp);
            }
        }
    };

    // prologue: stages 0,1
    {
        int t0 = c;
        if (t0 < ntn) issue(t0, 0);
        CP_COMMIT();
        int t1 = c + S;
        if (t1 < ntn) issue(t1, 1);
        CP_COMMIT();
    }

    // ---- per-warp addressing: 16 warps = 4(m) x 4(n), warp tile 32x32 ----
    const int wid = tid >> 5, lane = tid & 31;
    const int wm = wid & 3;
    const int wn = wid >> 2;
    const int lr = lane & 7, lq = lane >> 3;

    const uint32_t aRow = (uint32_t)(wm*32 + (lq & 1)*8 + lr);
    const uint32_t aCol = (uint32_t)((lq >> 1)*8);
    const uint32_t bRow = (uint32_t)(wn*32 + (lq >> 1)*8 + lr);
    const uint32_t bCol = (uint32_t)((lq & 1)*8);

    const uint32_t aB = sb + (aRow*KP + aCol)*2;
    uint32_t bB[3];
    #pragma unroll
    for (int s2 = 0; s2 < 3; s2++)
        bB[s2] = sb + (uint32_t)(1 + s2)*A_BY + (bRow*KP + bCol)*2;

    int phase = 0;
    for (int t = c; t < ntn; t += S, phase++) {
        const int slot = phase % 3;
        const int n0   = t * 128;

        CP_WAIT1();
        __syncthreads();

        // issue t+2S into the stage consumed at phase-1 (safe after barrier)
        const int tn = t + 2*S;
        if (tn < ntn) issue(tn, (phase + 2) % 3);
        CP_COMMIT();

        // ---- compute ----
        float acc[2][4][4];
        #pragma unroll
        for (int mt = 0; mt < 2; mt++)
            #pragma unroll
            for (int ns = 0; ns < 4; ns++)
                #pragma unroll
                for (int q = 0; q < 4; q++) acc[mt][ns][q] = 0.f;

        #pragma unroll
        for (int kc = 0; kc < KC; kc++) {
            const uint32_t kOff = (uint32_t)kc * 32;
            uint32_t ah[2][4], bh[2][4];
            #pragma unroll
            for (int mt = 0; mt < 2; mt++)
                ldsm4(ah[mt], aB + (uint32_t)(mt*16*KP)*2 + kOff);
            #pragma unroll
            for (int nb = 0; nb < 2; nb++)
                ldsm4(bh[nb], bB[slot] + (uint32_t)(nb*16*KP)*2 + kOff);
            #pragma unroll
            for (int mt = 0; mt < 2; mt++)
                #pragma unroll
                for (int ns = 0; ns < 4; ns++)
                    mma_fp16(acc[mt][ns], ah[mt], bh[ns>>1][(ns&1)*2], bh[ns>>1][(ns&1)*2+1]);
        }

        // ---- epilogue (all cols valid: 32000 % 128 == 0) ----
        const int r0 = m0 + wm*32 + (lane >> 2);
        const int c0 = n0 + wn*32 + (lane & 3)*2;
        #pragma unroll
        for (int mt = 0; mt < 2; mt++)
            #pragma unroll
            for (int ns = 0; ns < 4; ns++) {
                int row = r0 + mt*16;
                int col = c0 + ns*8;
                *reinterpret_cast<float2*>(C + (size_t)row*VV + col) =
                    make_float2(acc[mt][ns][0], acc[mt][ns][1]);
                *reinterpret_cast<float2*>(C + (size_t)(row+8)*VV + col) =
                    make_float2(acc[mt][ns][2], acc[mt][ns][3]);
            }
    }
}

// ---------------- launch ----------------
extern "C" void kernel_launch(void* const* d_in, const int* in_sizes, int n_in,
                              void* d_out, int out_size) {
    const int*   x      = (const int*)  d_in[0];
    const float* hidden = (const float*)d_in[1];
    const float* Wih0f  = (const float*)d_in[2];
    const float* Whh0f  = (const float*)d_in[3];
    const float* Wih0b  = (const float*)d_in[4];
    const float* Whh0b  = (const float*)d_in[5];
    const float* Wih1f  = (const float*)d_in[6];
    const float* Whh1f  = (const float*)d_in[7];
    const float* Wih1b  = (const float*)d_in[8];
    const float* Whh1b  = (const float*)d_in[9];
    const float* Wlin   = (const float*)d_in[10];

    float* out  = (float*)d_out;
    float* hout = out + (out_size - 4*BB*HH);

    void *p_gx0f, *p_gx0b, *p_y0, *p_gx1, *p_y1, *p_wl16;
    cudaGetSymbolAddress(&p_gx0f, g_gx0f);
    cudaGetSymbolAddress(&p_gx0b, g_gx0b);
    cudaGetSymbolAddress(&p_y0,   g_y0);
    cudaGetSymbolAddress(&p_gx1,  g_gx1);
    cudaGetSymbolAddress(&p_y1,   g_y1);
    cudaGetSymbolAddress(&p_wl16, g_wl16);

    cudaFuncSetAttribute(pg_gemm, cudaFuncAttributeMaxDynamicSharedMemorySize, SMEM3);
    cudaFuncSetAttribute(wl_gemm, cudaFuncAttributeMaxDynamicSharedMemorySize, WG_SMEM);

    // 0. pre-convert W_lin to fp16 (6.4M elems / 4 per thread / 256)
    convert_kernel<<<VV*KK/1024, 256>>>(Wlin);

    // 1. embedding gather
    gather_kernel<<<BB*TT, 2*GG>>>(x, Wih0f, Wih0b);

    // 2. GRU layer 0
    gru_kernel<<<64, 640>>>((const float*)p_gx0f, (const float*)p_gx0b, GG,
                            Whh0f, Whh0b, hidden, 0, (float*)p_y0, hout);

    // 3. fused layer-1 projections (bf16 3-pass; Ntot=600 -> 10 tiles)
    pg_gemm<<<dim3(5, 10), 512, SMEM3>>>((const float*)p_y0, Wih1f, Wih1b,
                                         GG, 2*GG, (float*)p_gx1, 2*GG);

    // 4. GRU layer 1 (combined gx1, stride 600)
    gru_kernel<<<64, 640>>>((const float*)p_gx1, (const float*)p_gx1 + GG, 2*GG,
                            Whh1f, Whh1b, hidden, 2, (float*)p_y1, hout);

    // 5. final projection: fp16 cp.async, 250 n-tiles x 5 m, grid 5x29
    wl_gemm<<<dim3(5, 29), 512, WG_SMEM>>>((const float*)p_y1,
                                           (const __half*)p_wl16, out);
}